// round 13
// baseline (speedup 1.0000x reference)
#include <cuda_runtime.h>
#include <cuda_bf16.h>
#include <stdint.h>
#include <math.h>

#define NN 10000
#define NE 160000

// ---------------- device scratch (static, allocation-free) ----------------
__device__ float g_t[NN * 16];
__device__ float g_qW[NN * 8];
// transposed, split weights [N, K] bf16
__device__ __align__(16) __nv_bfloat16 g_w1k_h[128 * 32], g_w1k_l[128 * 32];
__device__ __align__(16) __nv_bfloat16 g_w1v_h[128 * 32], g_w1v_l[128 * 32];
__device__ __align__(16) __nv_bfloat16 g_w2k_h[128 * 128], g_w2k_l[128 * 128];
__device__ __align__(16) __nv_bfloat16 g_w2v_h[128 * 128], g_w2v_l[128 * 128];
__device__ __align__(16) __nv_bfloat16 g_w3k_h[512 * 128], g_w3k_l[512 * 128];
__device__ __align__(16) __nv_bfloat16 g_w3v_h[1024 * 128], g_w3v_l[1024 * 128];
// fp32 tail
__device__ float g_vbuf[(size_t)NE * 16];
__device__ float g_logit[NE];
__device__ float g_m[NN];
__device__ float g_z[NN];
__device__ float g_agg[NN * 16];
__device__ float g_colsum[64];
__device__ float g_colsumsq[64];
__device__ float g_outpre[NN * 64];

// ---------------- helpers ----------------
__device__ __forceinline__ void atomicMaxF(float* addr, float v) {
    if (v >= 0.f)
        atomicMax((int*)addr, __float_as_int(v));
    else
        atomicMin((unsigned int*)addr, __float_as_uint(v));
}

__device__ __forceinline__ uint32_t smem_u32(const void* p) {
    uint32_t a;
    asm("{ .reg .u64 t; cvta.to.shared.u64 t, %1; cvt.u32.u64 %0, t; }" : "=r"(a) : "l"(p));
    return a;
}

__device__ __forceinline__ void split2(float x, __nv_bfloat16& h, __nv_bfloat16& l) {
    h = __float2bfloat16(x);
    l = __float2bfloat16(x - __bfloat162float(h));
}

__device__ __forceinline__ void ldm4(uint32_t* r, uint32_t addr) {
    asm volatile("ldmatrix.sync.aligned.m8n8.x4.shared.b16 {%0,%1,%2,%3}, [%4];"
                 : "=r"(r[0]), "=r"(r[1]), "=r"(r[2]), "=r"(r[3]) : "r"(addr));
}

__device__ __forceinline__ void mma16816(float* c, const uint32_t* a, const uint32_t* b) {
    asm volatile(
        "mma.sync.aligned.m16n8k16.row.col.f32.bf16.bf16.f32 "
        "{%0,%1,%2,%3}, {%4,%5,%6,%7}, {%8,%9}, {%0,%1,%2,%3};"
        : "+f"(c[0]), "+f"(c[1]), "+f"(c[2]), "+f"(c[3])
        : "r"(a[0]), "r"(a[1]), "r"(a[2]), "r"(a[3]), "r"(b[0]), "r"(b[1]));
}

#define CPA16(smaddr, gptr) \
    asm volatile("cp.async.ca.shared.global [%0], [%1], 16;" :: "r"(smaddr), "l"(gptr) : "memory")
#define CPA_COMMIT asm volatile("cp.async.commit_group;" ::: "memory")
#define CPA_WAIT0 asm volatile("cp.async.wait_group 0;" ::: "memory")

// async-copy a [64 rows x CPR*8 halves] weight block into smem at pitch PH (halves)
template <int CPR, int PH>
__device__ __forceinline__ void cpa_w(uint32_t bufh, uint32_t bufl,
                                      const __nv_bfloat16* gh, const __nv_bfloat16* gl,
                                      int tid) {
    constexpr int C = 64 * CPR;
    #pragma unroll
    for (int i = tid; i < C; i += 256) {
        int row = i / CPR, c8 = (i % CPR) * 8;
        uint32_t so = (uint32_t)(row * PH + c8) * 2;
        CPA16(bufh + so, (const char*)gh + (size_t)i * 16);
        CPA16(bufl + so, (const char*)gl + (size_t)i * 16);
    }
}

// 3-term split MMA, 16x32 warp tile (MT=1), hoisted fragments
template <int KS, int PITCH>
__device__ __forceinline__ void mma_tile(
    uint32_t aH, uint32_t aL, uint32_t bH, uint32_t bL,
    int lane, int wm, int wn, float c[4][4])
{
    #pragma unroll
    for (int kk = 0; kk < KS; kk++) {
        uint32_t ah[4], al[4], bh[2][4], bl[2][4];
        {
            int row = wm + (lane & 15);
            uint32_t off = (uint32_t)(row * PITCH + kk * 16 + 8 * (lane >> 4)) << 1;
            ldm4(ah, aH + off);
            ldm4(al, aL + off);
        }
        #pragma unroll
        for (int np = 0; np < 2; np++) {
            int row = wn + np * 16 + ((lane >> 4) << 3) + (lane & 7);
            uint32_t off = (uint32_t)(row * PITCH + kk * 16 + 8 * ((lane >> 3) & 1)) << 1;
            ldm4(bh[np], bH + off);
            ldm4(bl[np], bL + off);
        }
        #pragma unroll
        for (int nt = 0; nt < 4; nt++) {
            uint32_t bbh[2] = { bh[nt >> 1][(nt & 1) * 2], bh[nt >> 1][(nt & 1) * 2 + 1] };
            uint32_t bbl[2] = { bl[nt >> 1][(nt & 1) * 2], bl[nt >> 1][(nt & 1) * 2 + 1] };
            mma16816(c[nt], ah, bbh);
            mma16816(c[nt], ah, bbl);
            mma16816(c[nt], al, bbh);
        }
    }
}

// bias + relu + split-store a 16x32 fragment tile into [64][136] hi/lo smem, column base cb
__device__ __forceinline__ void epi_tile(
    float c[4][4], const float* __restrict__ bias,
    __nv_bfloat16* Dh, __nv_bfloat16* Dl, int lane, int wm, int wn, int cb)
{
    constexpr int P = 136;
    int r0 = wm + (lane >> 2);
    #pragma unroll
    for (int nt = 0; nt < 4; nt++) {
        int col = cb + wn + nt * 8 + (lane & 3) * 2;
        float b0 = __ldg(bias + col), b1 = __ldg(bias + col + 1);
        float v0 = fmaxf(c[nt][0] + b0, 0.f);
        float v1 = fmaxf(c[nt][1] + b1, 0.f);
        float v2 = fmaxf(c[nt][2] + b0, 0.f);
        float v3 = fmaxf(c[nt][3] + b1, 0.f);
        int lc = (col - cb) & 127;
        __nv_bfloat16 h0, l0, h1, l1;
        split2(v0, h0, l0); split2(v1, h1, l1);
        *(__nv_bfloat162*)&Dh[r0 * P + cb + lc] = __nv_bfloat162(h0, h1);
        *(__nv_bfloat162*)&Dl[r0 * P + cb + lc] = __nv_bfloat162(l0, l1);
        split2(v2, h0, l0); split2(v3, h1, l1);
        *(__nv_bfloat162*)&Dh[(r0 + 8) * P + cb + lc] = __nv_bfloat162(h0, h1);
        *(__nv_bfloat162*)&Dl[(r0 + 8) * P + cb + lc] = __nv_bfloat162(l0, l1);
    }
}

// ---------------- weight prep ----------------
__device__ __forceinline__ void wsplit_one(const float* src, __nv_bfloat16* dh,
                                           __nv_bfloat16* dl, int K, int N, int i) {
    int n = i / K, k = i % K;
    __nv_bfloat16 h, l;
    split2(src[k * N + n], h, l);
    dh[i] = h;
    dl[i] = l;
}

__global__ void wsplit_all(const float* __restrict__ Wk1, const float* __restrict__ Wv1,
                           const float* __restrict__ Wk2, const float* __restrict__ Wv2,
                           const float* __restrict__ Wk3, const float* __restrict__ Wv3)
{
    int i = blockIdx.x * 256 + threadIdx.x;
    if (i < 4096) { wsplit_one(Wk1, g_w1k_h, g_w1k_l, 32, 128, i); return; }
    i -= 4096;
    if (i < 4096) { wsplit_one(Wv1, g_w1v_h, g_w1v_l, 32, 128, i); return; }
    i -= 4096;
    if (i < 16384) { wsplit_one(Wk2, g_w2k_h, g_w2k_l, 128, 128, i); return; }
    i -= 16384;
    if (i < 16384) { wsplit_one(Wv2, g_w2v_h, g_w2v_l, 128, 128, i); return; }
    i -= 16384;
    if (i < 65536) { wsplit_one(Wk3, g_w3k_h, g_w3k_l, 128, 512, i); return; }
    i -= 65536;
    if (i < 131072) { wsplit_one(Wv3, g_w3v_h, g_w3v_l, 128, 1024, i); }
}

// ---------------- MLP chain + contraction, 64 edges/CTA, 2 CTAs/SM ----------------
// NOUT=16/NB=8: V path;  NOUT=8/NB=4: K path (logits)
template <int NOUT, int NB>
__device__ __forceinline__ void chain_body(
    char* sm,
    const float* __restrict__ edge_data,
    const __nv_bfloat16* __restrict__ W1h, const __nv_bfloat16* __restrict__ W1l,
    const float* __restrict__ b1,
    const __nv_bfloat16* __restrict__ W2h, const __nv_bfloat16* __restrict__ W2l,
    const float* __restrict__ b2,
    const __nv_bfloat16* __restrict__ W3h, const __nv_bfloat16* __restrict__ W3l,
    const float* __restrict__ b3,
    const int* __restrict__ ei, const float* __restrict__ sh)
{
    constexpr int P = 136, PA = 40;
    constexpr int NTOT = NB * 128;
    constexpr int NC = NB * 2;                  // 64-col chunks in phase 3
    constexpr int NSLOT = (NOUT == 16) ? 4 : 2;
    constexpr int PP = NOUT + 1;
    // arena (108544 B):
    __nv_bfloat16* H1h = (__nv_bfloat16*)(sm);              // [64][136]
    __nv_bfloat16* H1l = (__nv_bfloat16*)(sm + 17408);
    __nv_bfloat16* H2h = (__nv_bfloat16*)(sm + 34816);
    __nv_bfloat16* H2l = (__nv_bfloat16*)(sm + 52224);
    __nv_bfloat16* WBh = (__nv_bfloat16*)(sm + 69632);      // [64][136] single buffer
    __nv_bfloat16* WBl = (__nv_bfloat16*)(sm + 87040);
    // phase-1 overlays (inside H2 region; dead after phase 1)
    __nv_bfloat16* EAh = (__nv_bfloat16*)(sm + 34816);      // [64][40]
    __nv_bfloat16* EAl = (__nv_bfloat16*)(sm + 45056);
    // phase-1 W1 chunks (inside WB region)
    __nv_bfloat16* W1C0h = (__nv_bfloat16*)(sm + 69632);
    __nv_bfloat16* W1C0l = (__nv_bfloat16*)(sm + 74752);
    __nv_bfloat16* W1C1h = (__nv_bfloat16*)(sm + 79872);
    __nv_bfloat16* W1C1l = (__nv_bfloat16*)(sm + 84992);
    // phase-3 overlays (inside H1 region; dead after phase 2)
    float* u_s = (float*)sm;                                // [64][65]
    float* part = (float*)(sm + 16640);                     // [2][64][PP]
    float* bs = (float*)(sm + 104448);                      // bias3 (<=4096)

    const int tid = threadIdx.x, lane = tid & 31, warp = tid >> 5;
    const int m0 = blockIdx.x * 64;
    const int wm = (warp >> 1) * 16, wn = (warp & 1) * 32;  // 4m x 2n, 16x32 tiles

    const uint32_t sWBh = smem_u32(WBh), sWBl = smem_u32(WBl);
    float c[4][4];

    // ===== phase 1: h1 = relu(edge @ W1^T + b1), two 64-col chunks =====
    for (int i = tid; i < 64 * 8; i += 256) {
        int row = i >> 3, c4 = (i & 7) * 4;
        float4 v = *(const float4*)(edge_data + (size_t)(m0 + row) * 32 + c4);
        __nv_bfloat16 h[4], l[4];
        split2(v.x, h[0], l[0]); split2(v.y, h[1], l[1]);
        split2(v.z, h[2], l[2]); split2(v.w, h[3], l[3]);
        *(uint2*)&EAh[row * PA + c4] = *(uint2*)h;
        *(uint2*)&EAl[row * PA + c4] = *(uint2*)l;
    }
    cpa_w<4, PA>(smem_u32(W1C0h), smem_u32(W1C0l), W1h, W1l, tid);
    cpa_w<4, PA>(smem_u32(W1C1h), smem_u32(W1C1l), W1h + 64 * 32, W1l + 64 * 32, tid);
    CPA_COMMIT;
    CPA_WAIT0;
    __syncthreads();

    #pragma unroll
    for (int ch = 0; ch < 2; ch++) {
        #pragma unroll
        for (int nt = 0; nt < 4; nt++)
            #pragma unroll
            for (int j = 0; j < 4; j++) c[nt][j] = 0.f;
        mma_tile<2, PA>(smem_u32(EAh), smem_u32(EAl),
                        ch ? smem_u32(W1C1h) : smem_u32(W1C0h),
                        ch ? smem_u32(W1C1l) : smem_u32(W1C0l),
                        lane, wm, wn, c);
        epi_tile(c, b1, H1h, H1l, lane, wm, wn, ch * 64);
    }
    __syncthreads();   // h1 visible; EA + W1 buffers dead

    // ===== phase 2: h2 = relu(h1 @ W2^T + b2), two 64-col chunks =====
    #pragma unroll
    for (int ch = 0; ch < 2; ch++) {
        cpa_w<16, P>(sWBh, sWBl, W2h + (size_t)ch * 64 * 128, W2l + (size_t)ch * 64 * 128, tid);
        CPA_COMMIT;
        CPA_WAIT0;
        __syncthreads();   // chunk visible
        #pragma unroll
        for (int nt = 0; nt < 4; nt++)
            #pragma unroll
            for (int j = 0; j < 4; j++) c[nt][j] = 0.f;
        mma_tile<8, P>(smem_u32(H1h), smem_u32(H1l), sWBh, sWBl, lane, wm, wn, c);
        epi_tile(c, b2, H2h, H2l, lane, wm, wn, ch * 64);
        __syncthreads();   // all warps done reading WB (and, last iter, done with H1)
    }

    // ===== phase 3: layer-3 GEMM in 64-col chunks, fused contraction =====
    for (int i = tid; i < 64 * 64; i += 256) {
        int row = i >> 6, as = i & 63;
        int e = m0 + row;
        int src = ei[e];
        u_s[row * 65 + as] = g_t[src * 16 + (as >> 2)] * sh[e * 4 + (as & 3)] * 0.125f;
    }
    for (int i = tid; i < NTOT; i += 256) bs[i] = b3[i];

    float loc[2][NSLOT];
    #pragma unroll
    for (int s = 0; s < 2; s++)
        #pragma unroll
        for (int j = 0; j < NSLOT; j++) loc[s][j] = 0.f;

    const uint32_t sH2h = smem_u32(H2h), sH2l = smem_u32(H2l);

    for (int ch = 0; ch < NC; ch++) {
        if (ch) __syncthreads();   // prev mma done reading WB
        cpa_w<16, P>(sWBh, sWBl, W3h + (size_t)ch * 64 * 128, W3l + (size_t)ch * 64 * 128, tid);
        CPA_COMMIT;
        CPA_WAIT0;
        __syncthreads();           // chunk + (first iter) u_s/bs visible

        #pragma unroll
        for (int nt = 0; nt < 4; nt++)
            #pragma unroll
            for (int j = 0; j < 4; j++) c[nt][j] = 0.f;
        mma_tile<8, P>(sH2h, sH2l, sWBh, sWBl, lane, wm, wn, c);

        int r = wm + (lane >> 2);
        #pragma unroll
        for (int nt = 0; nt < 4; nt++) {
            int colb = ch * 64 + wn + nt * 8;
            int as = (NOUT == 16) ? (colb >> 4) : (colb >> 3);
            int obi = (NOUT == 16) ? ((nt & 1) * 2) : 0;
            float ur = u_s[r * 65 + as];
            float ur8 = u_s[(r + 8) * 65 + as];
            loc[0][obi]     += c[nt][0] * ur;
            loc[0][obi + 1] += c[nt][1] * ur;
            loc[1][obi]     += c[nt][2] * ur8;
            loc[1][obi + 1] += c[nt][3] * ur8;
        }
    }
    __syncthreads();

    // per-warp partials -> smem (2 n-warps)
    {
        int wi = warp & 1;
        #pragma unroll
        for (int s = 0; s < 2; s++) {
            int row = wm + s * 8 + (lane >> 2);
            #pragma unroll
            for (int j = 0; j < NSLOT; j++) {
                int ob = (lane & 3) * 2 + (j & 1) + (j >> 1) * 8;
                part[(wi * 64 + row) * PP + ob] = loc[s][j];
            }
        }
    }
    __syncthreads();

    if (NOUT == 16) {
        for (int idx = tid; idx < 64 * 16; idx += 256) {
            int row = idx >> 4, ob = idx & 15;
            float s = part[row * PP + ob] + part[(64 + row) * PP + ob];
            float bt = 0.f;
            #pragma unroll
            for (int as = 0; as < 64; as++) bt = fmaf(u_s[row * 65 + as], bs[as * 16 + ob], bt);
            g_vbuf[(size_t)(m0 + row) * 16 + ob] = s + bt;
        }
    } else {
        for (int idx = tid; idx < 64 * 8; idx += 256) {
            int row = idx >> 3, b = idx & 7;
            float s = part[row * PP + b] + part[(64 + row) * PP + b];
            float bt = 0.f;
            #pragma unroll
            for (int as = 0; as < 64; as++) bt = fmaf(u_s[row * 65 + as], bs[as * 8 + b], bt);
            part[row * PP + b] = s + bt;
        }
        __syncthreads();
        if (tid < 64) {
            int e = m0 + tid;
            int dst = ei[NE + e];
            float lp = 0.f;
            #pragma unroll
            for (int b = 0; b < 8; b++) lp += part[tid * PP + b] * g_qW[dst * 8 + b];
            g_logit[e] = lp;
            atomicMaxF(&g_m[dst], lp);
        }
    }
}

// one kernel runs the V chain then the K chain on the same 64 edges
__global__ __launch_bounds__(256, 2) void chain_both(
    const float* __restrict__ edge_data,
    const __nv_bfloat16* __restrict__ Wv1h, const __nv_bfloat16* __restrict__ Wv1l,
    const float* __restrict__ bv1,
    const __nv_bfloat16* __restrict__ Wv2h, const __nv_bfloat16* __restrict__ Wv2l,
    const float* __restrict__ bv2,
    const __nv_bfloat16* __restrict__ Wv3h, const __nv_bfloat16* __restrict__ Wv3l,
    const float* __restrict__ bv3,
    const __nv_bfloat16* __restrict__ Wk1h, const __nv_bfloat16* __restrict__ Wk1l,
    const float* __restrict__ bk1,
    const __nv_bfloat16* __restrict__ Wk2h, const __nv_bfloat16* __restrict__ Wk2l,
    const float* __restrict__ bk2,
    const __nv_bfloat16* __restrict__ Wk3h, const __nv_bfloat16* __restrict__ Wk3l,
    const float* __restrict__ bk3,
    const int* __restrict__ ei, const float* __restrict__ sh)
{
    extern __shared__ char sm[];
    chain_body<16, 8>(sm, edge_data, Wv1h, Wv1l, bv1, Wv2h, Wv2l, bv2,
                      Wv3h, Wv3l, bv3, ei, sh);
    __syncthreads();
    chain_body<8, 4>(sm, edge_data, Wk1h, Wk1l, bk1, Wk2h, Wk2l, bk2,
                     Wk3h, Wk3l, bk3, ei, sh);
}

// ---------------- init ----------------
__global__ void init_kernel() {
    int i = blockIdx.x * 256 + threadIdx.x;
    if (i < NN) { g_m[i] = -INFINITY; g_z[i] = 0.f; }
    if (i < NN * 16) g_agg[i] = 0.f;
    if (i < 64) { g_colsum[i] = 0.f; g_colsumsq[i] = 0.f; }
}

// ---------------- node linears ----------------
__global__ __launch_bounds__(128) void node_kernel(
    const float* __restrict__ node_data, const float* __restrict__ W_input,
    const float* __restrict__ W_query, const float* __restrict__ W_dot)
{
    __shared__ float Wi[64 * 16];
    __shared__ float Wq[16 * 8];
    __shared__ float Wd[64];
    __shared__ float tsh[8][16];
    __shared__ float qsh[8][8];
    int tid = threadIdx.x;
    for (int i = tid; i < 1024; i += 128) Wi[i] = W_input[i];
    if (tid < 128) Wq[tid] = W_query[tid];
    if (tid < 64) Wd[tid] = W_dot[tid];
    __syncthreads();

    int n_loc = tid >> 4, c = tid & 15;
    int n = blockIdx.x * 8 + n_loc;
    float tv = 0.f;
    if (n < NN) {
        const float* nd = node_data + (size_t)n * 64;
        #pragma unroll 8
        for (int i = 0; i < 64; i++) tv += nd[i] * Wi[i * 16 + c];
        tv *= 0.125f;
        g_t[n * 16 + c] = tv;
    }
    tsh[n_loc][c] = tv;
    __syncthreads();

    if (tid < 64) {
        int nl = tid >> 3, b = tid & 7;
        float qv = 0.f;
        #pragma unroll
        for (int a = 0; a < 16; a++) qv += tsh[nl][a] * Wq[a * 8 + b];
        qsh[nl][b] = qv * 0.25f;
    }
    __syncthreads();
    if (tid < 64) {
        int nl = tid >> 3, b = tid & 7;
        int n2 = blockIdx.x * 8 + nl;
        if (n2 < NN) {
            float s = 0.f;
            #pragma unroll
            for (int a = 0; a < 8; a++) s += qsh[nl][a] * Wd[a * 8 + b];
            g_qW[n2 * 8 + b] = s * 0.125f;
        }
    }
}

// ---------------- softmax numerator + segment sums ----------------
__global__ void attn_agg_kernel(const int* __restrict__ ei)
{
    int e = blockIdx.x * 256 + threadIdx.x;
    if (e >= NE) return;
    int dst = ei[NE + e];
    float p = expf(g_logit[e] - g_m[dst]);
    atomicAdd(&g_z[dst], p);
    const float* v = g_vbuf + (size_t)e * 16;
    float* agg = g_agg + dst * 16;
    #pragma unroll
    for (int c = 0; c < 16; c++) atomicAdd(&agg[c], p * v[c]);
}

// ---------------- output linear + residual + BN stats ----------------
__global__ __launch_bounds__(256) void out_stats_kernel(
    const float* __restrict__ node_data, const float* __restrict__ W_output)
{
    __shared__ float Wsh[16 * 64];
    __shared__ float red[256];
    int tid = threadIdx.x;
    for (int i = tid; i < 1024; i += 256) Wsh[i] = W_output[i];
    __syncthreads();

    int c = tid & 63;
    int r = tid >> 6;
    int n0 = blockIdx.x * 64;
    float lsum = 0.f, lsq = 0.f;
    for (int i = 0; i < 16; i++) {
        int n = n0 + r + i * 4;
        if (n < NN) {
            float zz = g_z[n];
            float inv = zz > 0.f ? 0.25f / zz : 0.f;
            float o = 0.f;
            const float* agg = g_agg + n * 16;
            #pragma unroll
            for (int j = 0; j < 16; j++) o += agg[j] * Wsh[j * 64 + c];
            o = o * inv + node_data[(size_t)n * 64 + c];
            g_outpre[(size_t)n * 64 + c] = o;
            lsum += o;
            lsq += o * o;
        }
    }
    red[tid] = lsum;
    __syncthreads();
    if (r == 0) atomicAdd(&g_colsum[c], red[c] + red[64 + c] + red[128 + c] + red[192 + c]);
    __syncthreads();
    red[tid] = lsq;
    __syncthreads();
    if (r == 0) atomicAdd(&g_colsumsq[c], red[c] + red[64 + c] + red[128 + c] + red[192 + c]);
}

// ---------------- batchnorm finalize ----------------
__global__ void bn_kernel(const float* __restrict__ bnw, const float* __restrict__ bnb,
                          float* __restrict__ out)
{
    int i = blockIdx.x * 256 + threadIdx.x;
    if (i >= NN * 64) return;
    int c = i & 63;
    const float invN = 1.f / NN;
    float mean = g_colsum[c] * invN;
    float var = g_colsumsq[c] * invN - mean * mean;
    out[i] = (g_outpre[i] - mean) * rsqrtf(var + 1e-5f) * bnw[c] + bnb[c];
}

// ---------------- launch ----------------
extern "C" void kernel_launch(void* const* d_in, const int* in_sizes, int n_in,
                              void* d_out, int out_size)
{
    const float* node_data = (const float*)d_in[0];
    const int*   edge_index = (const int*)d_in[1];
    const float* edge_data = (const float*)d_in[2];
    const float* edge_sh   = (const float*)d_in[3];
    const float* W_input = (const float*)d_in[4];
    const float* W_query = (const float*)d_in[5];
    const float* W_dot   = (const float*)d_in[6];
    const float* W_output = (const float*)d_in[7];
    const float* Wk1 = (const float*)d_in[8];
    const float* bk1 = (const float*)d_in[9];
    const float* Wk2 = (const float*)d_in[10];
    const float* bk2 = (const float*)d_in[11];
    const float* Wk3 = (const float*)d_in[12];
    const float* bk3 = (const float*)d_in[13];
    const float* Wv1 = (const float*)d_in[14];
    const float* bv1 = (const float*)d_in[15];
    const float* Wv2 = (const float*)d_in[16];
    const float* bv2 = (const float*)d_in[17];
    const float* Wv3 = (const float*)d_in[18];
    const float* bv3 = (const float*)d_in[19];
    const float* bn_weight = (const float*)d_in[20];
    const float* bn_bias   = (const float*)d_in[21];
    float* out = (float*)d_out;

    void *pw1kh, *pw1kl, *pw1vh, *pw1vl, *pw2kh, *pw2kl, *pw2vh, *pw2vl;
    void *pw3kh, *pw3kl, *pw3vh, *pw3vl;
    cudaGetSymbolAddress(&pw1kh, g_w1k_h); cudaGetSymbolAddress(&pw1kl, g_w1k_l);
    cudaGetSymbolAddress(&pw1vh, g_w1v_h); cudaGetSymbolAddress(&pw1vl, g_w1v_l);
    cudaGetSymbolAddress(&pw2kh, g_w2k_h); cudaGetSymbolAddress(&pw2kl, g_w2k_l);
    cudaGetSymbolAddress(&pw2vh, g_w2v_h); cudaGetSymbolAddress(&pw2vl, g_w2v_l);
    cudaGetSymbolAddress(&pw3kh, g_w3k_h); cudaGetSymbolAddress(&pw3kl, g_w3k_l);
    cudaGetSymbolAddress(&pw3vh, g_w3v_h); cudaGetSymbolAddress(&pw3vl, g_w3v_l);

    const int SMC = 108544;
    cudaFuncSetAttribute(chain_both, cudaFuncAttributeMaxDynamicSharedMemorySize, SMC);

    init_kernel<<<(NE + 255) / 256, 256>>>();                                   // 0
    wsplit_all<<<(237568 + 255) / 256, 256>>>(Wk1, Wv1, Wk2, Wv2, Wk3, Wv3);    // 1
    node_kernel<<<(NN + 7) / 8, 128>>>(node_data, W_input, W_query, W_dot);     // 2
    chain_both<<<NE / 64, 256, SMC>>>(                                          // 3
        edge_data,
        (const __nv_bfloat16*)pw1vh, (const __nv_bfloat16*)pw1vl, bv1,
        (const __nv_bfloat16*)pw2vh, (const __nv_bfloat16*)pw2vl, bv2,
        (const __nv_bfloat16*)pw3vh, (const __nv_bfloat16*)pw3vl, bv3,
        (const __nv_bfloat16*)pw1kh, (const __nv_bfloat16*)pw1kl, bk1,
        (const __nv_bfloat16*)pw2kh, (const __nv_bfloat16*)pw2kl, bk2,
        (const __nv_bfloat16*)pw3kh, (const __nv_bfloat16*)pw3kl, bk3,
        edge_index, edge_sh);

    attn_agg_kernel<<<(NE + 255) / 256, 256>>>(edge_index);                     // 4
    out_stats_kernel<<<(NN + 63) / 64, 256>>>(node_data, W_output);             // 5
    bn_kernel<<<(NN * 64 + 255) / 256, 256>>>(bn_weight, bn_bias, out);         // 6
}

// round 14
// speedup vs baseline: 1.0008x; 1.0008x over previous
#include <cuda_runtime.h>
#include <cuda_fp16.h>
#include <stdint.h>
#include <math.h>

#define NN 10000
#define NE 160000

// ---------------- device scratch (static, allocation-free) ----------------
__device__ float g_t[NN * 16];
__device__ float g_qW[NN * 8];
// transposed, split weights [N, K] fp16
__device__ __align__(16) __half g_w1k_h[128 * 32], g_w1k_l[128 * 32];
__device__ __align__(16) __half g_w1v_h[128 * 32], g_w1v_l[128 * 32];
__device__ __align__(16) __half g_w2k_h[128 * 128], g_w2k_l[128 * 128];
__device__ __align__(16) __half g_w2v_h[128 * 128], g_w2v_l[128 * 128];
__device__ __align__(16) __half g_w3k_h[512 * 128], g_w3k_l[512 * 128];
__device__ __align__(16) __half g_w3v_h[1024 * 128], g_w3v_l[1024 * 128];
// fp32 tail
__device__ float g_vbuf[(size_t)NE * 16];
__device__ float g_logit[NE];
__device__ float g_m[NN];
__device__ float g_z[NN];
__device__ float g_agg[NN * 16];
__device__ float g_colsum[64];
__device__ float g_colsumsq[64];
__device__ float g_outpre[NN * 64];

// ---------------- helpers ----------------
__device__ __forceinline__ void atomicMaxF(float* addr, float v) {
    if (v >= 0.f)
        atomicMax((int*)addr, __float_as_int(v));
    else
        atomicMin((unsigned int*)addr, __float_as_uint(v));
}

__device__ __forceinline__ uint32_t smem_u32(const void* p) {
    uint32_t a;
    asm("{ .reg .u64 t; cvta.to.shared.u64 t, %1; cvt.u32.u64 %0, t; }" : "=r"(a) : "l"(p));
    return a;
}

__device__ __forceinline__ void split2(float x, __half& h, __half& l) {
    h = __float2half_rn(x);
    l = __float2half_rn(x - __half2float(h));
}

__device__ __forceinline__ void ldm4(uint32_t* r, uint32_t addr) {
    asm volatile("ldmatrix.sync.aligned.m8n8.x4.shared.b16 {%0,%1,%2,%3}, [%4];"
                 : "=r"(r[0]), "=r"(r[1]), "=r"(r[2]), "=r"(r[3]) : "r"(addr));
}

// fp16 inputs, fp32 accumulate
__device__ __forceinline__ void mma_f32(float* c, const uint32_t* a, const uint32_t* b) {
    asm volatile(
        "mma.sync.aligned.m16n8k16.row.col.f32.f16.f16.f32 "
        "{%0,%1,%2,%3}, {%4,%5,%6,%7}, {%8,%9}, {%0,%1,%2,%3};"
        : "+f"(c[0]), "+f"(c[1]), "+f"(c[2]), "+f"(c[3])
        : "r"(a[0]), "r"(a[1]), "r"(a[2]), "r"(a[3]), "r"(b[0]), "r"(b[1]));
}
// fp16 inputs, fp16 accumulate (packed half2 x2)
__device__ __forceinline__ void mma_f16(uint32_t* c, const uint32_t* a, const uint32_t* b) {
    asm volatile(
        "mma.sync.aligned.m16n8k16.row.col.f16.f16.f16.f16 "
        "{%0,%1}, {%2,%3,%4,%5}, {%6,%7}, {%0,%1};"
        : "+r"(c[0]), "+r"(c[1])
        : "r"(a[0]), "r"(a[1]), "r"(a[2]), "r"(a[3]), "r"(b[0]), "r"(b[1]));
}

#define CPA16(smaddr, gptr) \
    asm volatile("cp.async.ca.shared.global [%0], [%1], 16;" :: "r"(smaddr), "l"(gptr) : "memory")
#define CPA_COMMIT asm volatile("cp.async.commit_group;" ::: "memory")
#define CPA_WAIT0 asm volatile("cp.async.wait_group 0;" ::: "memory")

// async-copy one 64-row x 128-col fp16 hi/lo chunk into a [64][136] smem buffer
__device__ __forceinline__ void cpa_chunk(uint32_t bufh, uint32_t bufl,
                                          const __half* gh, const __half* gl,
                                          int tid) {
    #pragma unroll
    for (int r = 0; r < 4; r++) {
        int i = tid + r * 256;
        int row = i >> 4, c8 = (i & 15) * 8;
        uint32_t so = (uint32_t)(row * 136 + c8) * 2;
        CPA16(bufh + so, (const char*)gh + (size_t)i * 16);
        CPA16(bufl + so, (const char*)gl + (size_t)i * 16);
    }
}

// 2-rate split MMA: main term fp32-acc + cross terms in a fp16 accumulator,
// folded into c at the end. MT m-tiles of 16, 32 n-cols.
template <int KS, int PITCH, int MT>
__device__ __forceinline__ void mma_block(
    uint32_t aH, uint32_t aL, uint32_t bH, uint32_t bL,
    int lane, int wm, int wn, float c[MT][4][4])
{
    uint32_t d[MT][4][2];
    #pragma unroll
    for (int mt = 0; mt < MT; mt++)
        #pragma unroll
        for (int nt = 0; nt < 4; nt++) { d[mt][nt][0] = 0u; d[mt][nt][1] = 0u; }

    #pragma unroll
    for (int kk = 0; kk < KS; kk++) {
        uint32_t ah[MT][4], al[MT][4], bh[2][4], bl[2][4];
        #pragma unroll
        for (int mt = 0; mt < MT; mt++) {
            int row = wm + mt * 16 + (lane & 15);
            uint32_t off = (uint32_t)(row * PITCH + kk * 16 + 8 * (lane >> 4)) << 1;
            ldm4(ah[mt], aH + off);
            ldm4(al[mt], aL + off);
        }
        #pragma unroll
        for (int np = 0; np < 2; np++) {
            int row = wn + np * 16 + ((lane >> 4) << 3) + (lane & 7);
            uint32_t off = (uint32_t)(row * PITCH + kk * 16 + 8 * ((lane >> 3) & 1)) << 1;
            ldm4(bh[np], bH + off);
            ldm4(bl[np], bL + off);
        }
        #pragma unroll
        for (int mt = 0; mt < MT; mt++)
            #pragma unroll
            for (int nt = 0; nt < 4; nt++) {
                uint32_t bbh[2] = { bh[nt >> 1][(nt & 1) * 2], bh[nt >> 1][(nt & 1) * 2 + 1] };
                uint32_t bbl[2] = { bl[nt >> 1][(nt & 1) * 2], bl[nt >> 1][(nt & 1) * 2 + 1] };
                mma_f32(c[mt][nt], ah[mt], bbh);       // main: fp32 acc
                mma_f16(d[mt][nt], ah[mt], bbl);       // cross: fp16 acc
                mma_f16(d[mt][nt], al[mt], bbh);
            }
    }
    // fold fp16 cross accumulators into fp32
    #pragma unroll
    for (int mt = 0; mt < MT; mt++)
        #pragma unroll
        for (int nt = 0; nt < 4; nt++) {
            float2 p0 = __half22float2(*(__half2*)&d[mt][nt][0]);
            float2 p1 = __half22float2(*(__half2*)&d[mt][nt][1]);
            c[mt][nt][0] += p0.x; c[mt][nt][1] += p0.y;
            c[mt][nt][2] += p1.x; c[mt][nt][3] += p1.y;
        }
}

// bias + relu + split-store fragments into a [*][136] hi/lo smem tile at column base cb
template <int MT>
__device__ __forceinline__ void epi_split_store(
    float c[MT][4][4], const float* __restrict__ bias,
    __half* Dh, __half* Dl, int lane, int wm, int wn, int cb)
{
    constexpr int P = 136;
    #pragma unroll
    for (int mt = 0; mt < MT; mt++) {
        int r0 = wm + mt * 16 + (lane >> 2);
        #pragma unroll
        for (int nt = 0; nt < 4; nt++) {
            int col = cb + wn + nt * 8 + (lane & 3) * 2;
            float b0 = __ldg(bias + col), b1 = __ldg(bias + col + 1);
            float v0 = fmaxf(c[mt][nt][0] + b0, 0.f);
            float v1 = fmaxf(c[mt][nt][1] + b1, 0.f);
            float v2 = fmaxf(c[mt][nt][2] + b0, 0.f);
            float v3 = fmaxf(c[mt][nt][3] + b1, 0.f);
            __half h0, l0, h1, l1;
            split2(v0, h0, l0); split2(v1, h1, l1);
            *(__half2*)&Dh[r0 * P + col] = __halves2half2(h0, h1);
            *(__half2*)&Dl[r0 * P + col] = __halves2half2(l0, l1);
            split2(v2, h0, l0); split2(v3, h1, l1);
            *(__half2*)&Dh[(r0 + 8) * P + col] = __halves2half2(h0, h1);
            *(__half2*)&Dl[(r0 + 8) * P + col] = __halves2half2(l0, l1);
        }
    }
}

// ---------------- weight prep ----------------
__device__ __forceinline__ void wsplit_one(const float* src, __half* dh,
                                           __half* dl, int K, int N, int i) {
    int n = i / K, k = i % K;
    __half h, l;
    split2(src[k * N + n], h, l);
    dh[i] = h;
    dl[i] = l;
}

__global__ void wsplit_all(const float* __restrict__ Wk1, const float* __restrict__ Wv1,
                           const float* __restrict__ Wk2, const float* __restrict__ Wv2,
                           const float* __restrict__ Wk3, const float* __restrict__ Wv3)
{
    int i = blockIdx.x * 256 + threadIdx.x;
    if (i < 4096) { wsplit_one(Wk1, g_w1k_h, g_w1k_l, 32, 128, i); return; }
    i -= 4096;
    if (i < 4096) { wsplit_one(Wv1, g_w1v_h, g_w1v_l, 32, 128, i); return; }
    i -= 4096;
    if (i < 16384) { wsplit_one(Wk2, g_w2k_h, g_w2k_l, 128, 128, i); return; }
    i -= 16384;
    if (i < 16384) { wsplit_one(Wv2, g_w2v_h, g_w2v_l, 128, 128, i); return; }
    i -= 16384;
    if (i < 65536) { wsplit_one(Wk3, g_w3k_h, g_w3k_l, 128, 512, i); return; }
    i -= 65536;
    if (i < 131072) { wsplit_one(Wv3, g_w3v_h, g_w3v_l, 128, 1024, i); }
}

// ---------------- full MLP chain + contraction (device body), 256 threads ----------------
// NOUT=16/NB=8: V path;  NOUT=8/NB=4: K path (logits)
template <int NOUT, int NB>
__device__ __forceinline__ void chain_body(
    char* sm,
    const float* __restrict__ edge_data,
    const __half* __restrict__ W1h, const __half* __restrict__ W1l,
    const float* __restrict__ b1,
    const __half* __restrict__ W2h, const __half* __restrict__ W2l,
    const float* __restrict__ b2,
    const __half* __restrict__ W3h, const __half* __restrict__ W3l,
    const float* __restrict__ b3,
    const int* __restrict__ ei, const float* __restrict__ sh)
{
    constexpr int P = 136, PA = 40;
    constexpr int NTOT = NB * 128;
    constexpr int NC = NB * 2;                  // 64-col chunks
    constexpr int NSLOT = (NOUT == 16) ? 4 : 2;
    constexpr int PP = NOUT + 1;
    __half* H1h = (__half*)(sm);
    __half* H1l = (__half*)(sm + 34816);
    // WB region: two 64-col double buffers (each h 17408 B + l 17408 B)
    __half* B0h = (__half*)(sm + 69632);
    __half* B0l = (__half*)(sm + 87040);
    __half* B1h = (__half*)(sm + 104448);
    __half* B1l = (__half*)(sm + 121856);
    __half* H2h = (__half*)(sm + 139264);
    __half* H2l = (__half*)(sm + 174080);
    __half* EAh = (__half*)(sm + 139264);           // phase-1 scratch
    __half* EAl = (__half*)(sm + 149504);
    __half* W1sh = (__half*)(sm + 159744);
    __half* W1sl = (__half*)(sm + 169984);
    float* u_s = (float*)sm;
    float* part = (float*)(sm + 33280);
    float* bs = (float*)(sm + 208896);

    const int tid = threadIdx.x, lane = tid & 31, warp = tid >> 5;
    const int m0 = blockIdx.x * 128;
    // phase-1 warp grid: 2(m) x 4(n), 64x32 tiles
    const int wm1 = (warp >> 2) * 64, wn1 = (warp & 3) * 32;
    // phase-2/3 warp grid: 4(m) x 2(n), 32x32 tiles
    const int wm2 = (warp >> 1) * 32, wn2 = (warp & 1) * 32;

    const uint32_t sB0h = smem_u32(B0h), sB0l = smem_u32(B0l);
    const uint32_t sB1h = smem_u32(B1h), sB1l = smem_u32(B1l);

    // ===== phase 1: h1 = relu(edge @ W1^T + b1) =====
    for (int i = tid; i < 128 * 8; i += 256) {
        int row = i >> 3, c4 = (i & 7) * 4;
        float4 v = *(const float4*)(edge_data + (size_t)(m0 + row) * 32 + c4);
        __half h[4], l[4];
        split2(v.x, h[0], l[0]); split2(v.y, h[1], l[1]);
        split2(v.z, h[2], l[2]); split2(v.w, h[3], l[3]);
        *(uint2*)&EAh[row * PA + c4] = *(uint2*)h;
        *(uint2*)&EAl[row * PA + c4] = *(uint2*)l;
    }
    for (int i = tid; i < 128 * 4; i += 256) {
        int row = i >> 2, c8 = (i & 3) * 8;
        *(uint4*)&W1sh[row * PA + c8] = ((const uint4*)W1h)[i];
        *(uint4*)&W1sl[row * PA + c8] = ((const uint4*)W1l)[i];
    }
    // async prefetch W2 (both 64-col chunks) into the double buffers
    cpa_chunk(sB0h, sB0l, W2h, W2l, tid);
    cpa_chunk(sB1h, sB1l, W2h + 64 * 128, W2l + 64 * 128, tid);
    CPA_COMMIT;
    __syncthreads();

    {
        float c1[4][4][4];
        #pragma unroll
        for (int mt = 0; mt < 4; mt++)
            #pragma unroll
            for (int nt = 0; nt < 4; nt++)
                #pragma unroll
                for (int j = 0; j < 4; j++) c1[mt][nt][j] = 0.f;
        mma_block<2, PA, 4>(smem_u32(EAh), smem_u32(EAl), smem_u32(W1sh), smem_u32(W1sl),
                            lane, wm1, wn1, c1);
        epi_split_store<4>(c1, b1, H1h, H1l, lane, wm1, wn1, 0);
    }
    CPA_WAIT0;
    __syncthreads();   // h1 + W2 chunks visible; phase-1 scratch reads done

    // ===== phase 2: h2 = relu(h1 @ W2^T + b2), two 64-col chunks =====
    #pragma unroll
    for (int ch = 0; ch < 2; ch++) {
        float c[2][4][4];
        #pragma unroll
        for (int mt = 0; mt < 2; mt++)
            #pragma unroll
            for (int nt = 0; nt < 4; nt++)
                #pragma unroll
                for (int j = 0; j < 4; j++) c[mt][nt][j] = 0.f;
        mma_block<8, P, 2>(smem_u32(H1h), smem_u32(H1l),
                           ch ? sB1h : sB0h, ch ? sB1l : sB0l,
                           lane, wm2, wn2, c);
        epi_split_store<2>(c, b2, H2h, H2l, lane, wm2, wn2, ch * 64);
    }
    __syncthreads();   // all warps done with H1/WB; h2 written

    // ===== phase 3: layer-3 GEMM streamed in 64-col chunks, fused contraction =====
    for (int i = tid; i < 128 * 64; i += 256) {
        int row = i >> 6, as = i & 63;
        int e = m0 + row;
        int src = ei[e];
        u_s[row * 65 + as] = g_t[src * 16 + (as >> 2)] * sh[e * 4 + (as & 3)] * 0.125f;
    }
    for (int i = tid; i < NTOT; i += 256) bs[i] = b3[i];
    cpa_chunk(sB0h, sB0l, W3h, W3l, tid);     // chunk 0
    CPA_COMMIT;

    float loc[4][NSLOT];
    #pragma unroll
    for (int s = 0; s < 4; s++)
        #pragma unroll
        for (int j = 0; j < NSLOT; j++) loc[s][j] = 0.f;

    const uint32_t sH2h = smem_u32(H2h), sH2l = smem_u32(H2l);

    for (int ch = 0; ch < NC; ch++) {
        CPA_WAIT0;
        __syncthreads();   // chunk ch visible; all warps done reading the other buffer
        if (ch + 1 < NC) {
            cpa_chunk((ch & 1) ? sB0h : sB1h, (ch & 1) ? sB0l : sB1l,
                      W3h + (size_t)(ch + 1) * 64 * 128,
                      W3l + (size_t)(ch + 1) * 64 * 128, tid);
            CPA_COMMIT;
        }

        float c[2][4][4];
        #pragma unroll
        for (int mt = 0; mt < 2; mt++)
            #pragma unroll
            for (int nt = 0; nt < 4; nt++)
                #pragma unroll
                for (int j = 0; j < 4; j++) c[mt][nt][j] = 0.f;
        mma_block<8, P, 2>(sH2h, sH2l,
                           (ch & 1) ? sB1h : sB0h, (ch & 1) ? sB1l : sB0l,
                           lane, wm2, wn2, c);

        #pragma unroll
        for (int mt = 0; mt < 2; mt++) {
            int r = wm2 + mt * 16 + (lane >> 2);
            #pragma unroll
            for (int nt = 0; nt < 4; nt++) {
                int colb = ch * 64 + wn2 + nt * 8;
                int as = (NOUT == 16) ? (colb >> 4) : (colb >> 3);
                int obi = (NOUT == 16) ? ((nt & 1) * 2) : 0;
                float ur = u_s[r * 65 + as];
                float ur8 = u_s[(r + 8) * 65 + as];
                loc[mt * 2][obi]         += c[mt][nt][0] * ur;
                loc[mt * 2][obi + 1]     += c[mt][nt][1] * ur;
                loc[mt * 2 + 1][obi]     += c[mt][nt][2] * ur8;
                loc[mt * 2 + 1][obi + 1] += c[mt][nt][3] * ur8;
            }
        }
    }

    // per-warp partials -> smem (2 n-warps per row)
    {
        int wi = warp & 1;
        #pragma unroll
        for (int s = 0; s < 4; s++) {
            int row = wm2 + (s >> 1) * 16 + (s & 1) * 8 + (lane >> 2);
            #pragma unroll
            for (int j = 0; j < NSLOT; j++) {
                int ob = (lane & 3) * 2 + (j & 1) + (j >> 1) * 8;
                part[(wi * 128 + row) * PP + ob] = loc[s][j];
            }
        }
    }
    __syncthreads();

    if (NOUT == 16) {
        for (int idx = tid; idx < 128 * 16; idx += 256) {
            int row = idx >> 4, ob = idx & 15;
            float s = part[row * PP + ob] + part[(128 + row) * PP + ob];
            float bt = 0.f;
            #pragma unroll
            for (int as = 0; as < 64; as++) bt = fmaf(u_s[row * 65 + as], bs[as * 16 + ob], bt);
            g_vbuf[(size_t)(m0 + row) * 16 + ob] = s + bt;
        }
    } else {
        for (int idx = tid; idx < 128 * 8; idx += 256) {
            int row = idx >> 3, b = idx & 7;
            float s = part[row * PP + b] + part[(128 + row) * PP + b];
            float bt = 0.f;
            #pragma unroll
            for (int as = 0; as < 64; as++) bt = fmaf(u_s[row * 65 + as], bs[as * 8 + b], bt);
            part[row * PP + b] = s + bt;
        }
        __syncthreads();
        if (tid < 128) {
            int e = m0 + tid;
            int dst = ei[NE + e];
            float lp = 0.f;
            #pragma unroll
            for (int b = 0; b < 8; b++) lp += part[tid * PP + b] * g_qW[dst * 8 + b];
            g_logit[e] = lp;
            atomicMaxF(&g_m[dst], lp);
        }
    }
}

// one kernel runs the V chain then the K chain on the same 128 edges
__global__ __launch_bounds__(256, 1) void chain_both(
    const float* __restrict__ edge_data,
    const __half* __restrict__ Wv1h, const __half* __restrict__ Wv1l,
    const float* __restrict__ bv1,
    const __half* __restrict__ Wv2h, const __half* __restrict__ Wv2l,
    const float* __restrict__ bv2,
    const __half* __restrict__ Wv3h, const __half* __restrict__ Wv3l,
    const float* __restrict__ bv3,
    const __half* __restrict__ Wk1h, const __half* __restrict__ Wk1l,
    const float* __restrict__ bk1,
    const __half* __restrict__ Wk2h, const __half* __restrict__ Wk2l,
    const float* __restrict__ bk2,
    const __half* __restrict__ Wk3h, const __half* __restrict__ Wk3l,
    const float* __restrict__ bk3,
    const int* __restrict__ ei, const float* __restrict__ sh)
{
    extern __shared__ char sm[];
    chain_body<16, 8>(sm, edge_data, Wv1h, Wv1l, bv1, Wv2h, Wv2l, bv2,
                      Wv3h, Wv3l, bv3, ei, sh);
    __syncthreads();
    chain_body<8, 4>(sm, edge_data, Wk1h, Wk1l, bk1, Wk2h, Wk2l, bk2,
                     Wk3h, Wk3l, bk3, ei, sh);
}

// ---------------- init ----------------
__global__ void init_kernel() {
    int i = blockIdx.x * 256 + threadIdx.x;
    if (i < NN) { g_m[i] = -INFINITY; g_z[i] = 0.f; }
    if (i < NN * 16) g_agg[i] = 0.f;
    if (i < 64) { g_colsum[i] = 0.f; g_colsumsq[i] = 0.f; }
}

// ---------------- node linears ----------------
__global__ __launch_bounds__(128) void node_kernel(
    const float* __restrict__ node_data, const float* __restrict__ W_input,
    const float* __restrict__ W_query, const float* __restrict__ W_dot)
{
    __shared__ float Wi[64 * 16];
    __shared__ float Wq[16 * 8];
    __shared__ float Wd[64];
    __shared__ float tsh[8][16];
    __shared__ float qsh[8][8];
    int tid = threadIdx.x;
    for (int i = tid; i < 1024; i += 128) Wi[i] = W_input[i];
    if (tid < 128) Wq[tid] = W_query[tid];
    if (tid < 64) Wd[tid] = W_dot[tid];
    __syncthreads();

    int n_loc = tid >> 4, c = tid & 15;
    int n = blockIdx.x * 8 + n_loc;
    float tv = 0.f;
    if (n < NN) {
        const float* nd = node_data + (size_t)n * 64;
        #pragma unroll 8
        for (int i = 0; i < 64; i++) tv += nd[i] * Wi[i * 16 + c];
        tv *= 0.125f;
        g_t[n * 16 + c] = tv;
    }
    tsh[n_loc][c] = tv;
    __syncthreads();

    if (tid < 64) {
        int nl = tid >> 3, b = tid & 7;
        float qv = 0.f;
        #pragma unroll
        for (int a = 0; a < 16; a++) qv += tsh[nl][a] * Wq[a * 8 + b];
        qsh[nl][b] = qv * 0.25f;
    }
    __syncthreads();
    if (tid < 64) {
        int nl = tid >> 3, b = tid & 7;
        int n2 = blockIdx.x * 8 + nl;
        if (n2 < NN) {
            float s = 0.f;
            #pragma unroll
            for (int a = 0; a < 8; a++) s += qsh[nl][a] * Wd[a * 8 + b];
            g_qW[n2 * 8 + b] = s * 0.125f;
        }
    }
}

// ---------------- softmax numerator + segment sums ----------------
__global__ void attn_agg_kernel(const int* __restrict__ ei)
{
    int e = blockIdx.x * 256 + threadIdx.x;
    if (e >= NE) return;
    int dst = ei[NE + e];
    float p = expf(g_logit[e] - g_m[dst]);
    atomicAdd(&g_z[dst], p);
    const float* v = g_vbuf + (size_t)e * 16;
    float* agg = g_agg + dst * 16;
    #pragma unroll
    for (int c = 0; c < 16; c++) atomicAdd(&agg[c], p * v[c]);
}

// ---------------- output linear + residual + BN stats ----------------
__global__ __launch_bounds__(256) void out_stats_kernel(
    const float* __restrict__ node_data, const float* __restrict__ W_output)
{
    __shared__ float Wsh[16 * 64];
    __shared__ float red[256];
    int tid = threadIdx.x;
    for (int i = tid; i < 1024; i += 256) Wsh[i] = W_output[i];
    __syncthreads();

    int c = tid & 63;
    int r = tid >> 6;
    int n0 = blockIdx.x * 64;
    float lsum = 0.f, lsq = 0.f;
    for (int i = 0; i < 16; i++) {
        int n = n0 + r + i * 4;
        if (n < NN) {
            float zz = g_z[n];
            float inv = zz > 0.f ? 0.25f / zz : 0.f;
            float o = 0.f;
            const float* agg = g_agg + n * 16;
            #pragma unroll
            for (int j = 0; j < 16; j++) o += agg[j] * Wsh[j * 64 + c];
            o = o * inv + node_data[(size_t)n * 64 + c];
            g_outpre[(size_t)n * 64 + c] = o;
            lsum += o;
            lsq += o * o;
        }
    }
    red[tid] = lsum;
    __syncthreads();
    if (r == 0) atomicAdd(&g_colsum[c], red[c] + red[64 + c] + red[128 + c] + red[192 + c]);
    __syncthreads();
    red[tid] = lsq;
    __syncthreads();
    if (r == 0) atomicAdd(&g_colsumsq[c], red[c] + red[64 + c] + red[128 + c] + red[192 + c]);
}

// ---------------- batchnorm finalize ----------------
__global__ void bn_kernel(const float* __restrict__ bnw, const float* __restrict__ bnb,
                          float* __restrict__ out)
{
    int i = blockIdx.x * 256 + threadIdx.x;
    if (i >= NN * 64) return;
    int c = i & 63;
    const float invN = 1.f / NN;
    float mean = g_colsum[c] * invN;
    float var = g_colsumsq[c] * invN - mean * mean;
    out[i] = (g_outpre[i] - mean) * rsqrtf(var + 1e-5f) * bnw[c] + bnb[c];
}

// ---------------- launch ----------------
extern "C" void kernel_launch(void* const* d_in, const int* in_sizes, int n_in,
                              void* d_out, int out_size)
{
    const float* node_data = (const float*)d_in[0];
    const int*   edge_index = (const int*)d_in[1];
    const float* edge_data = (const float*)d_in[2];
    const float* edge_sh   = (const float*)d_in[3];
    const float* W_input = (const float*)d_in[4];
    const float* W_query = (const float*)d_in[5];
    const float* W_dot   = (const float*)d_in[6];
    const float* W_output = (const float*)d_in[7];
    const float* Wk1 = (const float*)d_in[8];
    const float* bk1 = (const float*)d_in[9];
    const float* Wk2 = (const float*)d_in[10];
    const float* bk2 = (const float*)d_in[11];
    const float* Wk3 = (const float*)d_in[12];
    const float* bk3 = (const float*)d_in[13];
    const float* Wv1 = (const float*)d_in[14];
    const float* bv1 = (const float*)d_in[15];
    const float* Wv2 = (const float*)d_in[16];
    const float* bv2 = (const float*)d_in[17];
    const float* Wv3 = (const float*)d_in[18];
    const float* bv3 = (const float*)d_in[19];
    const float* bn_weight = (const float*)d_in[20];
    const float* bn_bias   = (const float*)d_in[21];
    float* out = (float*)d_out;

    void *pw1kh, *pw1kl, *pw1vh, *pw1vl, *pw2kh, *pw2kl, *pw2vh, *pw2vl;
    void *pw3kh, *pw3kl, *pw3vh, *pw3vl;
    cudaGetSymbolAddress(&pw1kh, g_w1k_h); cudaGetSymbolAddress(&pw1kl, g_w1k_l);
    cudaGetSymbolAddress(&pw1vh, g_w1v_h); cudaGetSymbolAddress(&pw1vl, g_w1v_l);
    cudaGetSymbolAddress(&pw2kh, g_w2k_h); cudaGetSymbolAddress(&pw2kl, g_w2k_l);
    cudaGetSymbolAddress(&pw2vh, g_w2v_h); cudaGetSymbolAddress(&pw2vl, g_w2v_l);
    cudaGetSymbolAddress(&pw3kh, g_w3k_h); cudaGetSymbolAddress(&pw3kl, g_w3k_l);
    cudaGetSymbolAddress(&pw3vh, g_w3v_h); cudaGetSymbolAddress(&pw3vl, g_w3v_l);

    const int SMC = 208896 + 4096;   // 212992
    cudaFuncSetAttribute(chain_both, cudaFuncAttributeMaxDynamicSharedMemorySize, SMC);

    init_kernel<<<(NE + 255) / 256, 256>>>();                                   // 0
    wsplit_all<<<(237568 + 255) / 256, 256>>>(Wk1, Wv1, Wk2, Wv2, Wk3, Wv3);    // 1
    node_kernel<<<(NN + 7) / 8, 128>>>(node_data, W_input, W_query, W_dot);     // 2
    chain_both<<<NE / 128, 256, SMC>>>(                                         // 3
        edge_data,
        (const __half*)pw1vh, (const __half*)pw1vl, bv1,
        (const __half*)pw2vh, (const __half*)pw2vl, bv2,
        (const __half*)pw3vh, (const __half*)pw3vl, bv3,
        (const __half*)pw1kh, (const __half*)pw1kl, bk1,
        (const __half*)pw2kh, (const __half*)pw2kl, bk2,
        (const __half*)pw3kh, (const __half*)pw3kl, bk3,
        edge_index, edge_sh);

    attn_agg_kernel<<<(NE + 255) / 256, 256>>>(edge_index);                     // 4
    out_stats_kernel<<<(NN + 63) / 64, 256>>>(node_data, W_output);             // 5
    bn_kernel<<<(NN * 64 + 255) / 256, 256>>>(bn_weight, bn_bias, out);         // 6
}

// round 15
// speedup vs baseline: 1.3950x; 1.3939x over previous
#include <cuda_runtime.h>
#include <cuda_fp16.h>
#include <stdint.h>
#include <math.h>

#define NN 10000
#define NE 160000

// ---------------- device scratch (static, allocation-free) ----------------
__device__ float g_t[NN * 16];
__device__ float g_qW[NN * 8];
// transposed weights [N, K], single fp16 (activations carry the split)
__device__ __align__(16) __half g_w1k[128 * 32], g_w1v[128 * 32];
__device__ __align__(16) __half g_w2k[128 * 128], g_w2v[128 * 128];
__device__ __align__(16) __half g_w3k[512 * 128], g_w3v[1024 * 128];
// fp32 tail
__device__ float g_vbuf[(size_t)NE * 16];
__device__ float g_logit[NE];
__device__ float g_m[NN];
__device__ float g_z[NN];
__device__ float g_agg[NN * 16];
__device__ float g_colsum[64];
__device__ float g_colsumsq[64];
__device__ float g_outpre[NN * 64];

// ---------------- helpers ----------------
__device__ __forceinline__ void atomicMaxF(float* addr, float v) {
    if (v >= 0.f)
        atomicMax((int*)addr, __float_as_int(v));
    else
        atomicMin((unsigned int*)addr, __float_as_uint(v));
}

__device__ __forceinline__ uint32_t smem_u32(const void* p) {
    uint32_t a;
    asm("{ .reg .u64 t; cvta.to.shared.u64 t, %1; cvt.u32.u64 %0, t; }" : "=r"(a) : "l"(p));
    return a;
}

__device__ __forceinline__ void split2(float x, __half& h, __half& l) {
    h = __float2half_rn(x);
    l = __float2half_rn(x - __half2float(h));
}

__device__ __forceinline__ void ldm4(uint32_t* r, uint32_t addr) {
    asm volatile("ldmatrix.sync.aligned.m8n8.x4.shared.b16 {%0,%1,%2,%3}, [%4];"
                 : "=r"(r[0]), "=r"(r[1]), "=r"(r[2]), "=r"(r[3]) : "r"(addr));
}

__device__ __forceinline__ void mma_f32(float* c, const uint32_t* a, const uint32_t* b) {
    asm volatile(
        "mma.sync.aligned.m16n8k16.row.col.f32.f16.f16.f32 "
        "{%0,%1,%2,%3}, {%4,%5,%6,%7}, {%8,%9}, {%0,%1,%2,%3};"
        : "+f"(c[0]), "+f"(c[1]), "+f"(c[2]), "+f"(c[3])
        : "r"(a[0]), "r"(a[1]), "r"(a[2]), "r"(a[3]), "r"(b[0]), "r"(b[1]));
}

#define CPA16(smaddr, gptr) \
    asm volatile("cp.async.ca.shared.global [%0], [%1], 16;" :: "r"(smaddr), "l"(gptr) : "memory")
#define CPA_COMMIT asm volatile("cp.async.commit_group;" ::: "memory")
#define CPA_WAIT0 asm volatile("cp.async.wait_group 0;" ::: "memory")

// async-copy one 64-row x 128-col fp16 chunk into a [64][136] smem buffer
__device__ __forceinline__ void cpa_chunk(uint32_t buf, const __half* g, int tid) {
    #pragma unroll
    for (int r = 0; r < 4; r++) {
        int i = tid + r * 256;
        int row = i >> 4, c8 = (i & 15) * 8;
        uint32_t so = (uint32_t)(row * 136 + c8) * 2;
        CPA16(buf + so, (const char*)g + (size_t)i * 16);
    }
}

// 2-term split MMA: c += Ah*B + Al*B (A split, B single fp16). MT m-tiles, 32 n-cols.
template <int KS, int PITCH, int MT>
__device__ __forceinline__ void mma_block(
    uint32_t aH, uint32_t aL, uint32_t bB,
    int lane, int wm, int wn, float c[MT][4][4])
{
    #pragma unroll
    for (int kk = 0; kk < KS; kk++) {
        uint32_t ah[MT][4], al[MT][4], bh[2][4];
        #pragma unroll
        for (int mt = 0; mt < MT; mt++) {
            int row = wm + mt * 16 + (lane & 15);
            uint32_t off = (uint32_t)(row * PITCH + kk * 16 + 8 * (lane >> 4)) << 1;
            ldm4(ah[mt], aH + off);
            ldm4(al[mt], aL + off);
        }
        #pragma unroll
        for (int np = 0; np < 2; np++) {
            int row = wn + np * 16 + ((lane >> 4) << 3) + (lane & 7);
            uint32_t off = (uint32_t)(row * PITCH + kk * 16 + 8 * ((lane >> 3) & 1)) << 1;
            ldm4(bh[np], bB + off);
        }
        #pragma unroll
        for (int mt = 0; mt < MT; mt++)
            #pragma unroll
            for (int nt = 0; nt < 4; nt++) {
                uint32_t bb[2] = { bh[nt >> 1][(nt & 1) * 2], bh[nt >> 1][(nt & 1) * 2 + 1] };
                mma_f32(c[mt][nt], ah[mt], bb);
                mma_f32(c[mt][nt], al[mt], bb);
            }
    }
}

// bias + relu + split-store fragments into a [*][136] hi/lo smem tile at column base cb
template <int MT>
__device__ __forceinline__ void epi_split_store(
    float c[MT][4][4], const float* __restrict__ bias,
    __half* Dh, __half* Dl, int lane, int wm, int wn, int cb)
{
    constexpr int P = 136;
    #pragma unroll
    for (int mt = 0; mt < MT; mt++) {
        int r0 = wm + mt * 16 + (lane >> 2);
        #pragma unroll
        for (int nt = 0; nt < 4; nt++) {
            int col = cb + wn + nt * 8 + (lane & 3) * 2;
            float b0 = __ldg(bias + col), b1 = __ldg(bias + col + 1);
            float v0 = fmaxf(c[mt][nt][0] + b0, 0.f);
            float v1 = fmaxf(c[mt][nt][1] + b1, 0.f);
            float v2 = fmaxf(c[mt][nt][2] + b0, 0.f);
            float v3 = fmaxf(c[mt][nt][3] + b1, 0.f);
            __half h0, l0, h1, l1;
            split2(v0, h0, l0); split2(v1, h1, l1);
            *(__half2*)&Dh[r0 * P + col] = __halves2half2(h0, h1);
            *(__half2*)&Dl[r0 * P + col] = __halves2half2(l0, l1);
            split2(v2, h0, l0); split2(v3, h1, l1);
            *(__half2*)&Dh[(r0 + 8) * P + col] = __halves2half2(h0, h1);
            *(__half2*)&Dl[(r0 + 8) * P + col] = __halves2half2(l0, l1);
        }
    }
}

// ---------------- weight prep: fp32 [K,N] -> fp16 [N,K] ----------------
__device__ __forceinline__ void wconv_one(const float* src, __half* d, int K, int N, int i) {
    int n = i / K, k = i % K;
    d[i] = __float2half_rn(src[k * N + n]);
}

__global__ void wconv_all(const float* __restrict__ Wk1, const float* __restrict__ Wv1,
                          const float* __restrict__ Wk2, const float* __restrict__ Wv2,
                          const float* __restrict__ Wk3, const float* __restrict__ Wv3)
{
    int i = blockIdx.x * 256 + threadIdx.x;
    if (i < 4096) { wconv_one(Wk1, g_w1k, 32, 128, i); return; }
    i -= 4096;
    if (i < 4096) { wconv_one(Wv1, g_w1v, 32, 128, i); return; }
    i -= 4096;
    if (i < 16384) { wconv_one(Wk2, g_w2k, 128, 128, i); return; }
    i -= 16384;
    if (i < 16384) { wconv_one(Wv2, g_w2v, 128, 128, i); return; }
    i -= 16384;
    if (i < 65536) { wconv_one(Wk3, g_w3k, 128, 512, i); return; }
    i -= 65536;
    if (i < 131072) { wconv_one(Wv3, g_w3v, 128, 1024, i); }
}

// ---------------- full MLP chain + contraction (device body), 256 threads ----------------
// NOUT=16/NB=8: V path;  NOUT=8/NB=4: K path (logits)
template <int NOUT, int NB>
__device__ __forceinline__ void chain_body(
    char* sm,
    const float* __restrict__ edge_data,
    const __half* __restrict__ W1, const float* __restrict__ b1,
    const __half* __restrict__ W2, const float* __restrict__ b2,
    const __half* __restrict__ W3, const float* __restrict__ b3,
    const int* __restrict__ ei, const float* __restrict__ sh)
{
    constexpr int P = 136, PA = 40;
    constexpr int NTOT = NB * 128;
    constexpr int NC = NB * 2;                  // 64-col chunks
    constexpr int NSLOT = (NOUT == 16) ? 4 : 2;
    constexpr int PP = NOUT + 1;
    // arena (178176 B)
    __half* H1h = (__half*)(sm);                    // [128][136]
    __half* H1l = (__half*)(sm + 34816);
    __half* B0  = (__half*)(sm + 69632);            // [64][136]
    __half* B1  = (__half*)(sm + 87040);
    __half* H2h = (__half*)(sm + 104448);
    __half* H2l = (__half*)(sm + 139264);
    // phase-1 overlays (inside H2 region; dead until phase 2 writes)
    __half* EAh = (__half*)(sm + 104448);           // [128][40]
    __half* EAl = (__half*)(sm + 114688);
    __half* W1s = (__half*)(sm + 124928);           // [128][40]
    // phase-3 overlays (inside H1 region)
    float* u_s = (float*)sm;                        // [128][65]
    float* part = (float*)(sm + 33280);             // [2][128][PP]
    float* bs = (float*)(sm + 174080);              // bias3 (<=4096)

    const int tid = threadIdx.x, lane = tid & 31, warp = tid >> 5;
    const int m0 = blockIdx.x * 128;
    // phase-1 warp grid: 2(m) x 4(n), 64x32 tiles
    const int wm1 = (warp >> 2) * 64, wn1 = (warp & 3) * 32;
    // phase-2/3 warp grid: 4(m) x 2(n), 32x32 tiles
    const int wm2 = (warp >> 1) * 32, wn2 = (warp & 1) * 32;

    const uint32_t sB0 = smem_u32(B0), sB1 = smem_u32(B1);

    // ===== phase 1: h1 = relu(edge @ W1^T + b1) =====
    for (int i = tid; i < 128 * 8; i += 256) {
        int row = i >> 3, c4 = (i & 7) * 4;
        float4 v = *(const float4*)(edge_data + (size_t)(m0 + row) * 32 + c4);
        __half h[4], l[4];
        split2(v.x, h[0], l[0]); split2(v.y, h[1], l[1]);
        split2(v.z, h[2], l[2]); split2(v.w, h[3], l[3]);
        *(uint2*)&EAh[row * PA + c4] = *(uint2*)h;
        *(uint2*)&EAl[row * PA + c4] = *(uint2*)l;
    }
    for (int i = tid; i < 128 * 4; i += 256) {
        int row = i >> 2, c8 = (i & 3) * 8;
        *(uint4*)&W1s[row * PA + c8] = ((const uint4*)W1)[i];
    }
    // async prefetch W2 (both 64-col chunks)
    cpa_chunk(sB0, W2, tid);
    cpa_chunk(sB1, W2 + 64 * 128, tid);
    CPA_COMMIT;
    __syncthreads();

    {
        float c1[4][4][4];
        #pragma unroll
        for (int mt = 0; mt < 4; mt++)
            #pragma unroll
            for (int nt = 0; nt < 4; nt++)
                #pragma unroll
                for (int j = 0; j < 4; j++) c1[mt][nt][j] = 0.f;
        mma_block<2, PA, 4>(smem_u32(EAh), smem_u32(EAl), smem_u32(W1s),
                            lane, wm1, wn1, c1);
        epi_split_store<4>(c1, b1, H1h, H1l, lane, wm1, wn1, 0);
    }
    CPA_WAIT0;
    __syncthreads();   // h1 + W2 chunks visible; phase-1 scratch reads done

    // ===== phase 2: h2 = relu(h1 @ W2^T + b2), two 64-col chunks =====
    #pragma unroll
    for (int ch = 0; ch < 2; ch++) {
        float c[2][4][4];
        #pragma unroll
        for (int mt = 0; mt < 2; mt++)
            #pragma unroll
            for (int nt = 0; nt < 4; nt++)
                #pragma unroll
                for (int j = 0; j < 4; j++) c[mt][nt][j] = 0.f;
        mma_block<8, P, 2>(smem_u32(H1h), smem_u32(H1l), ch ? sB1 : sB0,
                           lane, wm2, wn2, c);
        epi_split_store<2>(c, b2, H2h, H2l, lane, wm2, wn2, ch * 64);
    }
    __syncthreads();   // all warps done with H1/WB; h2 written

    // ===== phase 3: layer-3 GEMM streamed in 64-col chunks, fused contraction =====
    for (int i = tid; i < 128 * 64; i += 256) {
        int row = i >> 6, as = i & 63;
        int e = m0 + row;
        int src = ei[e];
        u_s[row * 65 + as] = g_t[src * 16 + (as >> 2)] * sh[e * 4 + (as & 3)] * 0.125f;
    }
    for (int i = tid; i < NTOT; i += 256) bs[i] = b3[i];
    cpa_chunk(sB0, W3, tid);     // chunk 0
    CPA_COMMIT;

    float loc[4][NSLOT];
    #pragma unroll
    for (int s = 0; s < 4; s++)
        #pragma unroll
        for (int j = 0; j < NSLOT; j++) loc[s][j] = 0.f;

    const uint32_t sH2h = smem_u32(H2h), sH2l = smem_u32(H2l);

    for (int ch = 0; ch < NC; ch++) {
        CPA_WAIT0;
        __syncthreads();   // chunk ch visible; all warps done reading the other buffer
        if (ch + 1 < NC) {
            cpa_chunk((ch & 1) ? sB0 : sB1, W3 + (size_t)(ch + 1) * 64 * 128, tid);
            CPA_COMMIT;
        }

        float c[2][4][4];
        #pragma unroll
        for (int mt = 0; mt < 2; mt++)
            #pragma unroll
            for (int nt = 0; nt < 4; nt++)
                #pragma unroll
                for (int j = 0; j < 4; j++) c[mt][nt][j] = 0.f;
        mma_block<8, P, 2>(sH2h, sH2l, (ch & 1) ? sB1 : sB0, lane, wm2, wn2, c);

        #pragma unroll
        for (int mt = 0; mt < 2; mt++) {
            int r = wm2 + mt * 16 + (lane >> 2);
            #pragma unroll
            for (int nt = 0; nt < 4; nt++) {
                int colb = ch * 64 + wn2 + nt * 8;
                int as = (NOUT == 16) ? (colb >> 4) : (colb >> 3);
                int obi = (NOUT == 16) ? ((nt & 1) * 2) : 0;
                float ur = u_s[r * 65 + as];
                float ur8 = u_s[(r + 8) * 65 + as];
                loc[mt * 2][obi]         += c[mt][nt][0] * ur;
                loc[mt * 2][obi + 1]     += c[mt][nt][1] * ur;
                loc[mt * 2 + 1][obi]     += c[mt][nt][2] * ur8;
                loc[mt * 2 + 1][obi + 1] += c[mt][nt][3] * ur8;
            }
        }
    }

    // per-warp partials -> smem (2 n-warps per row)
    {
        int wi = warp & 1;
        #pragma unroll
        for (int s = 0; s < 4; s++) {
            int row = wm2 + (s >> 1) * 16 + (s & 1) * 8 + (lane >> 2);
            #pragma unroll
            for (int j = 0; j < NSLOT; j++) {
                int ob = (lane & 3) * 2 + (j & 1) + (j >> 1) * 8;
                part[(wi * 128 + row) * PP + ob] = loc[s][j];
            }
        }
    }
    __syncthreads();

    if (NOUT == 16) {
        for (int idx = tid; idx < 128 * 16; idx += 256) {
            int row = idx >> 4, ob = idx & 15;
            float s = part[row * PP + ob] + part[(128 + row) * PP + ob];
            float bt = 0.f;
            #pragma unroll
            for (int as = 0; as < 64; as++) bt = fmaf(u_s[row * 65 + as], bs[as * 16 + ob], bt);
            g_vbuf[(size_t)(m0 + row) * 16 + ob] = s + bt;
        }
    } else {
        for (int idx = tid; idx < 128 * 8; idx += 256) {
            int row = idx >> 3, b = idx & 7;
            float s = part[row * PP + b] + part[(128 + row) * PP + b];
            float bt = 0.f;
            #pragma unroll
            for (int as = 0; as < 64; as++) bt = fmaf(u_s[row * 65 + as], bs[as * 8 + b], bt);
            part[row * PP + b] = s + bt;
        }
        __syncthreads();
        if (tid < 128) {
            int e = m0 + tid;
            int dst = ei[NE + e];
            float lp = 0.f;
            #pragma unroll
            for (int b = 0; b < 8; b++) lp += part[tid * PP + b] * g_qW[dst * 8 + b];
            g_logit[e] = lp;
            atomicMaxF(&g_m[dst], lp);
        }
    }
}

// one kernel runs the V chain then the K chain on the same 128 edges
__global__ __launch_bounds__(256, 1) void chain_both(
    const float* __restrict__ edge_data,
    const __half* __restrict__ Wv1, const float* __restrict__ bv1,
    const __half* __restrict__ Wv2, const float* __restrict__ bv2,
    const __half* __restrict__ Wv3, const float* __restrict__ bv3,
    const __half* __restrict__ Wk1, const float* __restrict__ bk1,
    const __half* __restrict__ Wk2, const float* __restrict__ bk2,
    const __half* __restrict__ Wk3, const float* __restrict__ bk3,
    const int* __restrict__ ei, const float* __restrict__ sh)
{
    extern __shared__ char sm[];
    chain_body<16, 8>(sm, edge_data, Wv1, bv1, Wv2, bv2, Wv3, bv3, ei, sh);
    __syncthreads();
    chain_body<8, 4>(sm, edge_data, Wk1, bk1, Wk2, bk2, Wk3, bk3, ei, sh);
}

// ---------------- init ----------------
__global__ void init_kernel() {
    int i = blockIdx.x * 256 + threadIdx.x;
    if (i < NN) { g_m[i] = -INFINITY; g_z[i] = 0.f; }
    if (i < NN * 16) g_agg[i] = 0.f;
    if (i < 64) { g_colsum[i] = 0.f; g_colsumsq[i] = 0.f; }
}

// ---------------- node linears ----------------
__global__ __launch_bounds__(128) void node_kernel(
    const float* __restrict__ node_data, const float* __restrict__ W_input,
    const float* __restrict__ W_query, const float* __restrict__ W_dot)
{
    __shared__ float Wi[64 * 16];
    __shared__ float Wq[16 * 8];
    __shared__ float Wd[64];
    __shared__ float tsh[8][16];
    __shared__ float qsh[8][8];
    int tid = threadIdx.x;
    for (int i = tid; i < 1024; i += 128) Wi[i] = W_input[i];
    if (tid < 128) Wq[tid] = W_query[tid];
    if (tid < 64) Wd[tid] = W_dot[tid];
    __syncthreads();

    int n_loc = tid >> 4, c = tid & 15;
    int n = blockIdx.x * 8 + n_loc;
    float tv = 0.f;
    if (n < NN) {
        const float* nd = node_data + (size_t)n * 64;
        #pragma unroll 8
        for (int i = 0; i < 64; i++) tv += nd[i] * Wi[i * 16 + c];
        tv *= 0.125f;
        g_t[n * 16 + c] = tv;
    }
    tsh[n_loc][c] = tv;
    __syncthreads();

    if (tid < 64) {
        int nl = tid >> 3, b = tid & 7;
        float qv = 0.f;
        #pragma unroll
        for (int a = 0; a < 16; a++) qv += tsh[nl][a] * Wq[a * 8 + b];
        qsh[nl][b] = qv * 0.25f;
    }
    __syncthreads();
    if (tid < 64) {
        int nl = tid >> 3, b = tid & 7;
        int n2 = blockIdx.x * 8 + nl;
        if (n2 < NN) {
            float s = 0.f;
            #pragma unroll
            for (int a = 0; a < 8; a++) s += qsh[nl][a] * Wd[a * 8 + b];
            g_qW[n2 * 8 + b] = s * 0.125f;
        }
    }
}

// ---------------- softmax numerator + segment sums ----------------
__global__ void attn_agg_kernel(const int* __restrict__ ei)
{
    int e = blockIdx.x * 256 + threadIdx.x;
    if (e >= NE) return;
    int dst = ei[NE + e];
    float p = expf(g_logit[e] - g_m[dst]);
    atomicAdd(&g_z[dst], p);
    const float* v = g_vbuf + (size_t)e * 16;
    float* agg = g_agg + dst * 16;
    #pragma unroll
    for (int c = 0; c < 16; c++) atomicAdd(&agg[c], p * v[c]);
}

// ---------------- output linear + residual + BN stats ----------------
__global__ __launch_bounds__(256) void out_stats_kernel(
    const float* __restrict__ node_data, const float* __restrict__ W_output)
{
    __shared__ float Wsh[16 * 64];
    __shared__ float red[256];
    int tid = threadIdx.x;
    for (int i = tid; i < 1024; i += 256) Wsh[i] = W_output[i];
    __syncthreads();

    int c = tid & 63;
    int r = tid >> 6;
    int n0 = blockIdx.x * 64;
    float lsum = 0.f, lsq = 0.f;
    for (int i = 0; i < 16; i++) {
        int n = n0 + r + i * 4;
        if (n < NN) {
            float zz = g_z[n];
            float inv = zz > 0.f ? 0.25f / zz : 0.f;
            float o = 0.f;
            const float* agg = g_agg + n * 16;
            #pragma unroll
            for (int j = 0; j < 16; j++) o += agg[j] * Wsh[j * 64 + c];
            o = o * inv + node_data[(size_t)n * 64 + c];
            g_outpre[(size_t)n * 64 + c] = o;
            lsum += o;
            lsq += o * o;
        }
    }
    red[tid] = lsum;
    __syncthreads();
    if (r == 0) atomicAdd(&g_colsum[c], red[c] + red[64 + c] + red[128 + c] + red[192 + c]);
    __syncthreads();
    red[tid] = lsq;
    __syncthreads();
    if (r == 0) atomicAdd(&g_colsumsq[c], red[c] + red[64 + c] + red[128 + c] + red[192 + c]);
}

// ---------------- batchnorm finalize ----------------
__global__ void bn_kernel(const float* __restrict__ bnw, const float* __restrict__ bnb,
                          float* __restrict__ out)
{
    int i = blockIdx.x * 256 + threadIdx.x;
    if (i >= NN * 64) return;
    int c = i & 63;
    const float invN = 1.f / NN;
    float mean = g_colsum[c] * invN;
    float var = g_colsumsq[c] * invN - mean * mean;
    out[i] = (g_outpre[i] - mean) * rsqrtf(var + 1e-5f) * bnw[c] + bnb[c];
}

// ---------------- launch ----------------
extern "C" void kernel_launch(void* const* d_in, const int* in_sizes, int n_in,
                              void* d_out, int out_size)
{
    const float* node_data = (const float*)d_in[0];
    const int*   edge_index = (const int*)d_in[1];
    const float* edge_data = (const float*)d_in[2];
    const float* edge_sh   = (const float*)d_in[3];
    const float* W_input = (const float*)d_in[4];
    const float* W_query = (const float*)d_in[5];
    const float* W_dot   = (const float*)d_in[6];
    const float* W_output = (const float*)d_in[7];
    const float* Wk1 = (const float*)d_in[8];
    const float* bk1 = (const float*)d_in[9];
    const float* Wk2 = (const float*)d_in[10];
    const float* bk2 = (const float*)d_in[11];
    const float* Wk3 = (const float*)d_in[12];
    const float* bk3 = (const float*)d_in[13];
    const float* Wv1 = (const float*)d_in[14];
    const float* bv1 = (const float*)d_in[15];
    const float* Wv2 = (const float*)d_in[16];
    const float* bv2 = (const float*)d_in[17];
    const float* Wv3 = (const float*)d_in[18];
    const float* bv3 = (const float*)d_in[19];
    const float* bn_weight = (const float*)d_in[20];
    const float* bn_bias   = (const float*)d_in[21];
    float* out = (float*)d_out;

    void *pw1k, *pw1v, *pw2k, *pw2v, *pw3k, *pw3v;
    cudaGetSymbolAddress(&pw1k, g_w1k); cudaGetSymbolAddress(&pw1v, g_w1v);
    cudaGetSymbolAddress(&pw2k, g_w2k); cudaGetSymbolAddress(&pw2v, g_w2v);
    cudaGetSymbolAddress(&pw3k, g_w3k); cudaGetSymbolAddress(&pw3v, g_w3v);

    const int SMC = 178176;
    cudaFuncSetAttribute(chain_both, cudaFuncAttributeMaxDynamicSharedMemorySize, SMC);

    init_kernel<<<(NE + 255) / 256, 256>>>();                                   // 0
    wconv_all<<<(237568 + 255) / 256, 256>>>(Wk1, Wv1, Wk2, Wv2, Wk3, Wv3);     // 1
    node_kernel<<<(NN + 7) / 8, 128>>>(node_data, W_input, W_query, W_dot);     // 2
    chain_both<<<NE / 128, 256, SMC>>>(                                         // 3
        edge_data,
        (const __half*)pw1v, bv1, (const __half*)pw2v, bv2, (const __half*)pw3v, bv3,
        (const __half*)pw1k, bk1, (const __half*)pw2k, bk2, (const __half*)pw3k, bk3,
        edge_index, edge_sh);

    attn_agg_kernel<<<(NE + 255) / 256, 256>>>(edge_index);                     // 4
    out_stats_kernel<<<(NN + 63) / 64, 256>>>(node_data, W_output);             // 5
    bn_kernel<<<(NN * 64 + 255) / 256, 256>>>(bn_weight, bn_bias, out);         // 6
}

// round 16
// speedup vs baseline: 1.9119x; 1.3706x over previous
#include <cuda_runtime.h>
#include <cuda_fp16.h>
#include <stdint.h>
#include <math.h>

#define NN 10000
#define NE 160000

// ---------------- device scratch (static, allocation-free) ----------------
__device__ float g_t[NN * 16];
__device__ float g_qW[NN * 8];
// transposed weights [N, K], fp16
__device__ __align__(16) __half g_w1k[128 * 32], g_w1v[128 * 32];
__device__ __align__(16) __half g_w2k[128 * 128], g_w2v[128 * 128];
__device__ __align__(16) __half g_w3k[512 * 128], g_w3v[1024 * 128];
// fp32 tail
__device__ float g_vbuf[(size_t)NE * 16];
__device__ float g_logit[NE];
__device__ float g_m[NN];
__device__ float g_z[NN];
__device__ float g_agg[NN * 16];
__device__ float g_colsum[64];
__device__ float g_colsumsq[64];
__device__ float g_outpre[NN * 64];

// ---------------- helpers ----------------
__device__ __forceinline__ void atomicMaxF(float* addr, float v) {
    if (v >= 0.f)
        atomicMax((int*)addr, __float_as_int(v));
    else
        atomicMin((unsigned int*)addr, __float_as_uint(v));
}

__device__ __forceinline__ uint32_t smem_u32(const void* p) {
    uint32_t a;
    asm("{ .reg .u64 t; cvta.to.shared.u64 t, %1; cvt.u32.u64 %0, t; }" : "=r"(a) : "l"(p));
    return a;
}

__device__ __forceinline__ void ldm4(uint32_t* r, uint32_t addr) {
    asm volatile("ldmatrix.sync.aligned.m8n8.x4.shared.b16 {%0,%1,%2,%3}, [%4];"
                 : "=r"(r[0]), "=r"(r[1]), "=r"(r[2]), "=r"(r[3]) : "r"(addr));
}

__device__ __forceinline__ void mma_f32(float* c, const uint32_t* a, const uint32_t* b) {
    asm volatile(
        "mma.sync.aligned.m16n8k16.row.col.f32.f16.f16.f32 "
        "{%0,%1,%2,%3}, {%4,%5,%6,%7}, {%8,%9}, {%0,%1,%2,%3};"
        : "+f"(c[0]), "+f"(c[1]), "+f"(c[2]), "+f"(c[3])
        : "r"(a[0]), "r"(a[1]), "r"(a[2]), "r"(a[3]), "r"(b[0]), "r"(b[1]));
}

#define CPA16(smaddr, gptr) \
    asm volatile("cp.async.ca.shared.global [%0], [%1], 16;" :: "r"(smaddr), "l"(gptr) : "memory")
#define CPA_COMMIT asm volatile("cp.async.commit_group;" ::: "memory")
#define CPA_WAIT0 asm volatile("cp.async.wait_group 0;" ::: "memory")

// async-copy one 64-row x 128-col fp16 chunk into a [64][136] smem buffer
__device__ __forceinline__ void cpa_chunk(uint32_t buf, const __half* g, int tid) {
    #pragma unroll
    for (int r = 0; r < 4; r++) {
        int i = tid + r * 256;
        int row = i >> 4, c8 = (i & 15) * 8;
        uint32_t so = (uint32_t)(row * 136 + c8) * 2;
        CPA16(buf + so, (const char*)g + (size_t)i * 16);
    }
}

// single-term fp16 MMA: c += A*B. MT m-tiles of 16, 32 n-cols.
template <int KS, int PITCH, int MT>
__device__ __forceinline__ void mma_block(
    uint32_t aB, uint32_t bB,
    int lane, int wm, int wn, float c[MT][4][4])
{
    #pragma unroll
    for (int kk = 0; kk < KS; kk++) {
        uint32_t a[MT][4], bh[2][4];
        #pragma unroll
        for (int mt = 0; mt < MT; mt++) {
            int row = wm + mt * 16 + (lane & 15);
            uint32_t off = (uint32_t)(row * PITCH + kk * 16 + 8 * (lane >> 4)) << 1;
            ldm4(a[mt], aB + off);
        }
        #pragma unroll
        for (int np = 0; np < 2; np++) {
            int row = wn + np * 16 + ((lane >> 4) << 3) + (lane & 7);
            uint32_t off = (uint32_t)(row * PITCH + kk * 16 + 8 * ((lane >> 3) & 1)) << 1;
            ldm4(bh[np], bB + off);
        }
        #pragma unroll
        for (int mt = 0; mt < MT; mt++)
            #pragma unroll
            for (int nt = 0; nt < 4; nt++) {
                uint32_t bb[2] = { bh[nt >> 1][(nt & 1) * 2], bh[nt >> 1][(nt & 1) * 2 + 1] };
                mma_f32(c[mt][nt], a[mt], bb);
            }
    }
}

// bias + relu + fp16-store fragments into a [*][136] smem tile at column base cb
template <int MT>
__device__ __forceinline__ void epi_store(
    float c[MT][4][4], const float* __restrict__ bias,
    __half* D, int lane, int wm, int wn, int cb)
{
    constexpr int P = 136;
    #pragma unroll
    for (int mt = 0; mt < MT; mt++) {
        int r0 = wm + mt * 16 + (lane >> 2);
        #pragma unroll
        for (int nt = 0; nt < 4; nt++) {
            int col = cb + wn + nt * 8 + (lane & 3) * 2;
            float b0 = __ldg(bias + col), b1 = __ldg(bias + col + 1);
            float v0 = fmaxf(c[mt][nt][0] + b0, 0.f);
            float v1 = fmaxf(c[mt][nt][1] + b1, 0.f);
            float v2 = fmaxf(c[mt][nt][2] + b0, 0.f);
            float v3 = fmaxf(c[mt][nt][3] + b1, 0.f);
            *(__half2*)&D[r0 * P + col] =
                __halves2half2(__float2half_rn(v0), __float2half_rn(v1));
            *(__half2*)&D[(r0 + 8) * P + col] =
                __halves2half2(__float2half_rn(v2), __float2half_rn(v3));
        }
    }
}

// ---------------- weight prep: fp32 [K,N] -> fp16 [N,K] ----------------
__device__ __forceinline__ void wconv_one(const float* src, __half* d, int K, int N, int i) {
    int n = i / K, k = i % K;
    d[i] = __float2half_rn(src[k * N + n]);
}

__global__ void wconv_all(const float* __restrict__ Wk1, const float* __restrict__ Wv1,
                          const float* __restrict__ Wk2, const float* __restrict__ Wv2,
                          const float* __restrict__ Wk3, const float* __restrict__ Wv3)
{
    int i = blockIdx.x * 256 + threadIdx.x;
    if (i < 4096) { wconv_one(Wk1, g_w1k, 32, 128, i); return; }
    i -= 4096;
    if (i < 4096) { wconv_one(Wv1, g_w1v, 32, 128, i); return; }
    i -= 4096;
    if (i < 16384) { wconv_one(Wk2, g_w2k, 128, 128, i); return; }
    i -= 16384;
    if (i < 16384) { wconv_one(Wv2, g_w2v, 128, 128, i); return; }
    i -= 16384;
    if (i < 65536) { wconv_one(Wk3, g_w3k, 128, 512, i); return; }
    i -= 65536;
    if (i < 131072) { wconv_one(Wv3, g_w3v, 128, 1024, i); }
}

// ---------------- full MLP chain + contraction (device body), 256 threads ----------------
// NOUT=16/NB=8: V path;  NOUT=8/NB=4: K path (logits)
template <int NOUT, int NB>
__device__ __forceinline__ void chain_body(
    char* sm,
    const float* __restrict__ edge_data,
    const __half* __restrict__ W1, const float* __restrict__ b1,
    const __half* __restrict__ W2, const float* __restrict__ b2,
    const __half* __restrict__ W3, const float* __restrict__ b3,
    const int* __restrict__ ei, const float* __restrict__ sh)
{
    constexpr int P = 136, PA = 40;
    constexpr int NTOT = NB * 128;
    constexpr int NC = NB * 2;                  // 64-col chunks
    constexpr int NSLOT = (NOUT == 16) ? 4 : 2;
    constexpr int PP = NOUT + 1;
    // arena (125952 B)
    __half* H1 = (__half*)(sm);                     // [128][136]
    __half* H2 = (__half*)(sm + 34816);             // [128][136]
    __half* B0 = (__half*)(sm + 69632);             // [64][136]
    __half* B1 = (__half*)(sm + 87040);             // [64][136]
    float* bs  = (float*)(sm + 104448);             // bias3 (<=4096)
    float* part = (float*)(sm + 108544);            // [2][128][PP] (<=17408)
    // phase-1 overlays (inside H2 region; dead until phase 2 writes)
    __half* EA  = (__half*)(sm + 34816);            // [128][40]
    __half* W1s = (__half*)(sm + 45056);            // [128][40]
    // phase-3 overlay (inside H1 region; dead after phase 2)
    float* u_s = (float*)sm;                        // [128][65]

    const int tid = threadIdx.x, lane = tid & 31, warp = tid >> 5;
    const int m0 = blockIdx.x * 128;
    // phase-1 warp grid: 2(m) x 4(n), 64x32 tiles
    const int wm1 = (warp >> 2) * 64, wn1 = (warp & 3) * 32;
    // phase-2/3 warp grid: 4(m) x 2(n), 32x32 tiles
    const int wm2 = (warp >> 1) * 32, wn2 = (warp & 1) * 32;

    const uint32_t sB0 = smem_u32(B0), sB1 = smem_u32(B1);

    // ===== phase 1: h1 = relu(edge @ W1^T + b1) =====
    for (int i = tid; i < 128 * 8; i += 256) {
        int row = i >> 3, c4 = (i & 7) * 4;
        float4 v = *(const float4*)(edge_data + (size_t)(m0 + row) * 32 + c4);
        __half h[4];
        h[0] = __float2half_rn(v.x); h[1] = __float2half_rn(v.y);
        h[2] = __float2half_rn(v.z); h[3] = __float2half_rn(v.w);
        *(uint2*)&EA[row * PA + c4] = *(uint2*)h;
    }
    for (int i = tid; i < 128 * 4; i += 256) {
        int row = i >> 2, c8 = (i & 3) * 8;
        *(uint4*)&W1s[row * PA + c8] = ((const uint4*)W1)[i];
    }
    // async prefetch W2 (both 64-col chunks)
    cpa_chunk(sB0, W2, tid);
    cpa_chunk(sB1, W2 + 64 * 128, tid);
    CPA_COMMIT;
    __syncthreads();

    {
        float c1[4][4][4];
        #pragma unroll
        for (int mt = 0; mt < 4; mt++)
            #pragma unroll
            for (int nt = 0; nt < 4; nt++)
                #pragma unroll
                for (int j = 0; j < 4; j++) c1[mt][nt][j] = 0.f;
        mma_block<2, PA, 4>(smem_u32(EA), smem_u32(W1s), lane, wm1, wn1, c1);
        epi_store<4>(c1, b1, H1, lane, wm1, wn1, 0);
    }
    CPA_WAIT0;
    __syncthreads();   // h1 + W2 chunks visible; phase-1 scratch reads done

    // ===== phase 2: h2 = relu(h1 @ W2^T + b2), two 64-col chunks =====
    #pragma unroll
    for (int ch = 0; ch < 2; ch++) {
        float c[2][4][4];
        #pragma unroll
        for (int mt = 0; mt < 2; mt++)
            #pragma unroll
            for (int nt = 0; nt < 4; nt++)
                #pragma unroll
                for (int j = 0; j < 4; j++) c[mt][nt][j] = 0.f;
        mma_block<8, P, 2>(smem_u32(H1), ch ? sB1 : sB0, lane, wm2, wn2, c);
        epi_store<2>(c, b2, H2, lane, wm2, wn2, ch * 64);
    }
    __syncthreads();   // all warps done with H1/WB; h2 written

    // ===== phase 3: layer-3 GEMM streamed in 64-col chunks, fused contraction =====
    for (int i = tid; i < 128 * 64; i += 256) {
        int row = i >> 6, as = i & 63;
        int e = m0 + row;
        int src = ei[e];
        u_s[row * 65 + as] = g_t[src * 16 + (as >> 2)] * sh[e * 4 + (as & 3)] * 0.125f;
    }
    for (int i = tid; i < NTOT; i += 256) bs[i] = b3[i];
    cpa_chunk(sB0, W3, tid);     // chunk 0
    CPA_COMMIT;

    float loc[4][NSLOT];
    #pragma unroll
    for (int s = 0; s < 4; s++)
        #pragma unroll
        for (int j = 0; j < NSLOT; j++) loc[s][j] = 0.f;

    const uint32_t sH2 = smem_u32(H2);

    for (int ch = 0; ch < NC; ch++) {
        CPA_WAIT0;
        __syncthreads();   // chunk ch visible; all warps done reading the other buffer
        if (ch + 1 < NC) {
            cpa_chunk((ch & 1) ? sB0 : sB1, W3 + (size_t)(ch + 1) * 64 * 128, tid);
            CPA_COMMIT;
        }

        float c[2][4][4];
        #pragma unroll
        for (int mt = 0; mt < 2; mt++)
            #pragma unroll
            for (int nt = 0; nt < 4; nt++)
                #pragma unroll
                for (int j = 0; j < 4; j++) c[mt][nt][j] = 0.f;
        mma_block<8, P, 2>(sH2, (ch & 1) ? sB1 : sB0, lane, wm2, wn2, c);

        #pragma unroll
        for (int mt = 0; mt < 2; mt++) {
            int r = wm2 + mt * 16 + (lane >> 2);
            #pragma unroll
            for (int nt = 0; nt < 4; nt++) {
                int colb = ch * 64 + wn2 + nt * 8;
                int as = (NOUT == 16) ? (colb >> 4) : (colb >> 3);
                int obi = (NOUT == 16) ? ((nt & 1) * 2) : 0;
                float ur = u_s[r * 65 + as];
                float ur8 = u_s[(r + 8) * 65 + as];
                loc[mt * 2][obi]         += c[mt][nt][0] * ur;
                loc[mt * 2][obi + 1]     += c[mt][nt][1] * ur;
                loc[mt * 2 + 1][obi]     += c[mt][nt][2] * ur8;
                loc[mt * 2 + 1][obi + 1] += c[mt][nt][3] * ur8;
            }
        }
    }

    // per-warp partials -> smem (2 n-warps per row)
    {
        int wi = warp & 1;
        #pragma unroll
        for (int s = 0; s < 4; s++) {
            int row = wm2 + (s >> 1) * 16 + (s & 1) * 8 + (lane >> 2);
            #pragma unroll
            for (int j = 0; j < NSLOT; j++) {
                int ob = (lane & 3) * 2 + (j & 1) + (j >> 1) * 8;
                part[(wi * 128 + row) * PP + ob] = loc[s][j];
            }
        }
    }
    __syncthreads();

    if (NOUT == 16) {
        for (int idx = tid; idx < 128 * 16; idx += 256) {
            int row = idx >> 4, ob = idx & 15;
            float s = part[row * PP + ob] + part[(128 + row) * PP + ob];
            float bt = 0.f;
            #pragma unroll
            for (int as = 0; as < 64; as++) bt = fmaf(u_s[row * 65 + as], bs[as * 16 + ob], bt);
            g_vbuf[(size_t)(m0 + row) * 16 + ob] = s + bt;
        }
    } else {
        for (int idx = tid; idx < 128 * 8; idx += 256) {
            int row = idx >> 3, b = idx & 7;
            float s = part[row * PP + b] + part[(128 + row) * PP + b];
            float bt = 0.f;
            #pragma unroll
            for (int as = 0; as < 64; as++) bt = fmaf(u_s[row * 65 + as], bs[as * 8 + b], bt);
            part[row * PP + b] = s + bt;
        }
        __syncthreads();
        if (tid < 128) {
            int e = m0 + tid;
            int dst = ei[NE + e];
            float lp = 0.f;
            #pragma unroll
            for (int b = 0; b < 8; b++) lp += part[tid * PP + b] * g_qW[dst * 8 + b];
            g_logit[e] = lp;
            atomicMaxF(&g_m[dst], lp);
        }
    }
}

// one kernel runs the V chain then the K chain on the same 128 edges
__global__ __launch_bounds__(256, 1) void chain_both(
    const float* __restrict__ edge_data,
    const __half* __restrict__ Wv1, const float* __restrict__ bv1,
    const __half* __restrict__ Wv2, const float* __restrict__ bv2,
    const __half* __restrict__ Wv3, const float* __restrict__ bv3,
    const __half* __restrict__ Wk1, const float* __restrict__ bk1,
    const __half* __restrict__ Wk2, const float* __restrict__ bk2,
    const __half* __restrict__ Wk3, const float* __restrict__ bk3,
    const int* __restrict__ ei, const float* __restrict__ sh)
{
    extern __shared__ char sm[];
    chain_body<16, 8>(sm, edge_data, Wv1, bv1, Wv2, bv2, Wv3, bv3, ei, sh);
    __syncthreads();
    chain_body<8, 4>(sm, edge_data, Wk1, bk1, Wk2, bk2, Wk3, bk3, ei, sh);
}

// ---------------- init ----------------
__global__ void init_kernel() {
    int i = blockIdx.x * 256 + threadIdx.x;
    if (i < NN) { g_m[i] = -INFINITY; g_z[i] = 0.f; }
    if (i < NN * 16) g_agg[i] = 0.f;
    if (i < 64) { g_colsum[i] = 0.f; g_colsumsq[i] = 0.f; }
}

// ---------------- node linears ----------------
__global__ __launch_bounds__(128) void node_kernel(
    const float* __restrict__ node_data, const float* __restrict__ W_input,
    const float* __restrict__ W_query, const float* __restrict__ W_dot)
{
    __shared__ float Wi[64 * 16];
    __shared__ float Wq[16 * 8];
    __shared__ float Wd[64];
    __shared__ float tsh[8][16];
    __shared__ float qsh[8][8];
    int tid = threadIdx.x;
    for (int i = tid; i < 1024; i += 128) Wi[i] = W_input[i];
    if (tid < 128) Wq[tid] = W_query[tid];
    if (tid < 64) Wd[tid] = W_dot[tid];
    __syncthreads();

    int n_loc = tid >> 4, c = tid & 15;
    int n = blockIdx.x * 8 + n_loc;
    float tv = 0.f;
    if (n < NN) {
        const float* nd = node_data + (size_t)n * 64;
        #pragma unroll 8
        for (int i = 0; i < 64; i++) tv += nd[i] * Wi[i * 16 + c];
        tv *= 0.125f;
        g_t[n * 16 + c] = tv;
    }
    tsh[n_loc][c] = tv;
    __syncthreads();

    if (tid < 64) {
        int nl = tid >> 3, b = tid & 7;
        float qv = 0.f;
        #pragma unroll
        for (int a = 0; a < 16; a++) qv += tsh[nl][a] * Wq[a * 8 + b];
        qsh[nl][b] = qv * 0.25f;
    }
    __syncthreads();
    if (tid < 64) {
        int nl = tid >> 3, b = tid & 7;
        int n2 = blockIdx.x * 8 + nl;
        if (n2 < NN) {
            float s = 0.f;
            #pragma unroll
            for (int a = 0; a < 8; a++) s += qsh[nl][a] * Wd[a * 8 + b];
            g_qW[n2 * 8 + b] = s * 0.125f;
        }
    }
}

// ---------------- softmax numerator + segment sums ----------------
__global__ void attn_agg_kernel(const int* __restrict__ ei)
{
    int e = blockIdx.x * 256 + threadIdx.x;
    if (e >= NE) return;
    int dst = ei[NE + e];
    float p = expf(g_logit[e] - g_m[dst]);
    atomicAdd(&g_z[dst], p);
    const float* v = g_vbuf + (size_t)e * 16;
    float* agg = g_agg + dst * 16;
    #pragma unroll
    for (int c = 0; c < 16; c++) atomicAdd(&agg[c], p * v[c]);
}

// ---------------- output linear + residual + BN stats ----------------
__global__ __launch_bounds__(256) void out_stats_kernel(
    const float* __restrict__ node_data, const float* __restrict__ W_output)
{
    __shared__ float Wsh[16 * 64];
    __shared__ float red[256];
    int tid = threadIdx.x;
    for (int i = tid; i < 1024; i += 256) Wsh[i] = W_output[i];
    __syncthreads();

    int c = tid & 63;
    int r = tid >> 6;
    int n0 = blockIdx.x * 64;
    float lsum = 0.f, lsq = 0.f;
    for (int i = 0; i < 16; i++) {
        int n = n0 + r + i * 4;
        if (n < NN) {
            float zz = g_z[n];
            float inv = zz > 0.f ? 0.25f / zz : 0.f;
            float o = 0.f;
            const float* agg = g_agg + n * 16;
            #pragma unroll
            for (int j = 0; j < 16; j++) o += agg[j] * Wsh[j * 64 + c];
            o = o * inv + node_data[(size_t)n * 64 + c];
            g_outpre[(size_t)n * 64 + c] = o;
            lsum += o;
            lsq += o * o;
        }
    }
    red[tid] = lsum;
    __syncthreads();
    if (r == 0) atomicAdd(&g_colsum[c], red[c] + red[64 + c] + red[128 + c] + red[192 + c]);
    __syncthreads();
    red[tid] = lsq;
    __syncthreads();
    if (r == 0) atomicAdd(&g_colsumsq[c], red[c] + red[64 + c] + red[128 + c] + red[192 + c]);
}

// ---------------- batchnorm finalize ----------------
__global__ void bn_kernel(const float* __restrict__ bnw, const float* __restrict__ bnb,
                          float* __restrict__ out)
{
    int i = blockIdx.x * 256 + threadIdx.x;
    if (i >= NN * 64) return;
    int c = i & 63;
    const float invN = 1.f / NN;
    float mean = g_colsum[c] * invN;
    float var = g_colsumsq[c] * invN - mean * mean;
    out[i] = (g_outpre[i] - mean) * rsqrtf(var + 1e-5f) * bnw[c] + bnb[c];
}

// ---------------- launch ----------------
extern "C" void kernel_launch(void* const* d_in, const int* in_sizes, int n_in,
                              void* d_out, int out_size)
{
    const float* node_data = (const float*)d_in[0];
    const int*   edge_index = (const int*)d_in[1];
    const float* edge_data = (const float*)d_in[2];
    const float* edge_sh   = (const float*)d_in[3];
    const float* W_input = (const float*)d_in[4];
    const float* W_query = (const float*)d_in[5];
    const float* W_dot   = (const float*)d_in[6];
    const float* W_output = (const float*)d_in[7];
    const float* Wk1 = (const float*)d_in[8];
    const float* bk1 = (const float*)d_in[9];
    const float* Wk2 = (const float*)d_in[10];
    const float* bk2 = (const float*)d_in[11];
    const float* Wk3 = (const float*)d_in[12];
    const float* bk3 = (const float*)d_in[13];
    const float* Wv1 = (const float*)d_in[14];
    const float* bv1 = (const float*)d_in[15];
    const float* Wv2 = (const float*)d_in[16];
    const float* bv2 = (const float*)d_in[17];
    const float* Wv3 = (const float*)d_in[18];
    const float* bv3 = (const float*)d_in[19];
    const float* bn_weight = (const float*)d_in[20];
    const float* bn_bias   = (const float*)d_in[21];
    float* out = (float*)d_out;

    void *pw1k, *pw1v, *pw2k, *pw2v, *pw3k, *pw3v;
    cudaGetSymbolAddress(&pw1k, g_w1k); cudaGetSymbolAddress(&pw1v, g_w1v);
    cudaGetSymbolAddress(&pw2k, g_w2k); cudaGetSymbolAddress(&pw2v, g_w2v);
    cudaGetSymbolAddress(&pw3k, g_w3k); cudaGetSymbolAddress(&pw3v, g_w3v);

    const int SMC = 125952;
    cudaFuncSetAttribute(chain_both, cudaFuncAttributeMaxDynamicSharedMemorySize, SMC);

    init_kernel<<<(NE + 255) / 256, 256>>>();                                   // 0
    wconv_all<<<(237568 + 255) / 256, 256>>>(Wk1, Wv1, Wk2, Wv2, Wk3, Wv3);     // 1
    node_kernel<<<(NN + 7) / 8, 128>>>(node_data, W_input, W_query, W_dot);     // 2
    chain_both<<<NE / 128, 256, SMC>>>(                                         // 3
        edge_data,
        (const __half*)pw1v, bv1, (const __half*)pw2v, bv2, (const __half*)pw3v, bv3,
        (const __half*)pw1k, bk1, (const __half*)pw2k, bk2, (const __half*)pw3k, bk3,
        edge_index, edge_sh);

    attn_agg_kernel<<<(NE + 255) / 256, 256>>>(edge_index);                     // 4
    out_stats_kernel<<<(NN + 63) / 64, 256>>>(node_data, W_output);             // 5
    bn_kernel<<<(NN * 64 + 255) / 256, 256>>>(bn_weight, bn_bias, out);         // 6
}

// round 17
// speedup vs baseline: 2.2234x; 1.1629x over previous
#include <cuda_runtime.h>
#include <cuda_fp16.h>
#include <stdint.h>
#include <math.h>

#define NN 10000
#define NE 160000

// ---------------- device scratch (static, allocation-free) ----------------
__device__ float g_t[NN * 16];
__device__ float g_qW[NN * 8];
// transposed weights [N, K], fp16
__device__ __align__(16) __half g_w1k[128 * 32], g_w1v[128 * 32];
__device__ __align__(16) __half g_w2k[128 * 128], g_w2v[128 * 128];
__device__ __align__(16) __half g_w3k[512 * 128], g_w3v[1024 * 128];
// fp32 tail
__device__ float g_vbuf[(size_t)NE * 16];
__device__ float g_logit[NE];
__device__ float g_m[NN];
__device__ float g_z[NN];
__device__ float g_agg[NN * 16];
__device__ float g_colsum[64];
__device__ float g_colsumsq[64];
__device__ float g_outpre[NN * 64];

// ---------------- helpers ----------------
__device__ __forceinline__ void atomicMaxF(float* addr, float v) {
    if (v >= 0.f)
        atomicMax((int*)addr, __float_as_int(v));
    else
        atomicMin((unsigned int*)addr, __float_as_uint(v));
}

__device__ __forceinline__ uint32_t smem_u32(const void* p) {
    uint32_t a;
    asm("{ .reg .u64 t; cvta.to.shared.u64 t, %1; cvt.u32.u64 %0, t; }" : "=r"(a) : "l"(p));
    return a;
}

__device__ __forceinline__ void ldm4(uint32_t* r, uint32_t addr) {
    asm volatile("ldmatrix.sync.aligned.m8n8.x4.shared.b16 {%0,%1,%2,%3}, [%4];"
                 : "=r"(r[0]), "=r"(r[1]), "=r"(r[2]), "=r"(r[3]) : "r"(addr));
}

__device__ __forceinline__ void mma_f32(float* c, const uint32_t* a, const uint32_t* b) {
    asm volatile(
        "mma.sync.aligned.m16n8k16.row.col.f32.f16.f16.f32 "
        "{%0,%1,%2,%3}, {%4,%5,%6,%7}, {%8,%9}, {%0,%1,%2,%3};"
        : "+f"(c[0]), "+f"(c[1]), "+f"(c[2]), "+f"(c[3])
        : "r"(a[0]), "r"(a[1]), "r"(a[2]), "r"(a[3]), "r"(b[0]), "r"(b[1]));
}

#define CPA16(smaddr, gptr) \
    asm volatile("cp.async.ca.shared.global [%0], [%1], 16;" :: "r"(smaddr), "l"(gptr) : "memory")
#define CPA_COMMIT asm volatile("cp.async.commit_group;" ::: "memory")
#define CPA_WAIT0 asm volatile("cp.async.wait_group 0;" ::: "memory")

// async-copy one 64-row x 128-col fp16 chunk into a [64][136] smem buffer
__device__ __forceinline__ void cpa_chunk(uint32_t buf, const __half* g, int tid) {
    #pragma unroll
    for (int r = 0; r < 4; r++) {
        int i = tid + r * 256;
        int row = i >> 4, c8 = (i & 15) * 8;
        uint32_t so = (uint32_t)(row * 136 + c8) * 2;
        CPA16(buf + so, (const char*)g + (size_t)i * 16);
    }
}

// single-term fp16 MMA: c += A*B. MT m-tiles of 16, 32 n-cols.
template <int KS, int PITCH, int MT>
__device__ __forceinline__ void mma_block(
    uint32_t aB, uint32_t bB,
    int lane, int wm, int wn, float c[MT][4][4])
{
    #pragma unroll
    for (int kk = 0; kk < KS; kk++) {
        uint32_t a[MT][4], bh[2][4];
        #pragma unroll
        for (int mt = 0; mt < MT; mt++) {
            int row = wm + mt * 16 + (lane & 15);
            uint32_t off = (uint32_t)(row * PITCH + kk * 16 + 8 * (lane >> 4)) << 1;
            ldm4(a[mt], aB + off);
        }
        #pragma unroll
        for (int np = 0; np < 2; np++) {
            int row = wn + np * 16 + ((lane >> 4) << 3) + (lane & 7);
            uint32_t off = (uint32_t)(row * PITCH + kk * 16 + 8 * ((lane >> 3) & 1)) << 1;
            ldm4(bh[np], bB + off);
        }
        #pragma unroll
        for (int mt = 0; mt < MT; mt++)
            #pragma unroll
            for (int nt = 0; nt < 4; nt++) {
                uint32_t bb[2] = { bh[nt >> 1][(nt & 1) * 2], bh[nt >> 1][(nt & 1) * 2 + 1] };
                mma_f32(c[mt][nt], a[mt], bb);
            }
    }
}

// bias + relu + fp16-store fragments into a [*][136] smem tile at column base cb
template <int MT>
__device__ __forceinline__ void epi_store(
    float c[MT][4][4], const float* __restrict__ bias,
    __half* D, int lane, int wm, int wn, int cb)
{
    constexpr int P = 136;
    #pragma unroll
    for (int mt = 0; mt < MT; mt++) {
        int r0 = wm + mt * 16 + (lane >> 2);
        #pragma unroll
        for (int nt = 0; nt < 4; nt++) {
            int col = cb + wn + nt * 8 + (lane & 3) * 2;
            float b0 = __ldg(bias + col), b1 = __ldg(bias + col + 1);
            float v0 = fmaxf(c[mt][nt][0] + b0, 0.f);
            float v1 = fmaxf(c[mt][nt][1] + b1, 0.f);
            float v2 = fmaxf(c[mt][nt][2] + b0, 0.f);
            float v3 = fmaxf(c[mt][nt][3] + b1, 0.f);
            *(__half2*)&D[r0 * P + col] =
                __halves2half2(__float2half_rn(v0), __float2half_rn(v1));
            *(__half2*)&D[(r0 + 8) * P + col] =
                __halves2half2(__float2half_rn(v2), __float2half_rn(v3));
        }
    }
}

// ---------------- weight prep: fp32 [K,N] -> fp16 [N,K] ----------------
__device__ __forceinline__ void wconv_one(const float* src, __half* d, int K, int N, int i) {
    int n = i / K, k = i % K;
    d[i] = __float2half_rn(src[k * N + n]);
}

__global__ void wconv_all(const float* __restrict__ Wk1, const float* __restrict__ Wv1,
                          const float* __restrict__ Wk2, const float* __restrict__ Wv2,
                          const float* __restrict__ Wk3, const float* __restrict__ Wv3)
{
    int i = blockIdx.x * 256 + threadIdx.x;
    if (i < 4096) { wconv_one(Wk1, g_w1k, 32, 128, i); return; }
    i -= 4096;
    if (i < 4096) { wconv_one(Wv1, g_w1v, 32, 128, i); return; }
    i -= 4096;
    if (i < 16384) { wconv_one(Wk2, g_w2k, 128, 128, i); return; }
    i -= 16384;
    if (i < 16384) { wconv_one(Wv2, g_w2v, 128, 128, i); return; }
    i -= 16384;
    if (i < 65536) { wconv_one(Wk3, g_w3k, 128, 512, i); return; }
    i -= 65536;
    if (i < 131072) { wconv_one(Wv3, g_w3v, 128, 1024, i); }
}

// ---------------- full MLP chain + contraction (device body), 256 threads ----------------
// NOUT=16/NB=8: V path;  NOUT=8/NB=4: K path (logits)
template <int NOUT, int NB>
__device__ __forceinline__ void chain_body(
    char* sm,
    const float* __restrict__ edge_data,
    const __half* __restrict__ W1, const float* __restrict__ b1,
    const __half* __restrict__ W2, const float* __restrict__ b2,
    const __half* __restrict__ W3, const float* __restrict__ b3,
    const int* __restrict__ ei, const float* __restrict__ sh)
{
    constexpr int P = 136, PA = 40;
    constexpr int NTOT = NB * 128;
    constexpr int NC = NB * 2;                  // 64-col chunks
    constexpr int NSLOT = (NOUT == 16) ? 4 : 2;
    constexpr int PP = NOUT + 1;
    // arena (108544 B): H1 | H2 | B0 | B1 | bs
    __half* H1 = (__half*)(sm);                     // [128][136]
    __half* H2 = (__half*)(sm + 34816);             // [128][136]
    __half* B0 = (__half*)(sm + 69632);             // [64][136]
    __half* B1 = (__half*)(sm + 87040);             // [64][136]
    float* bs  = (float*)(sm + 104448);             // bias3 (<=4096)
    // phase-1 overlays (inside H2 region; dead until phase 2 writes)
    __half* EA  = (__half*)(sm + 34816);            // [128][40]
    __half* W1s = (__half*)(sm + 45056);            // [128][40]
    // phase-3 overlays: u_s in H1 (dead after phase 2); part in B0 (dead after last chunk mma)
    float* u_s = (float*)sm;                        // [128][65] = 33280
    float* part = (float*)(sm + 69632);             // [2][128][PP] <= 17408

    const int tid = threadIdx.x, lane = tid & 31, warp = tid >> 5;
    const int m0 = blockIdx.x * 128;
    // phase-1 warp grid: 2(m) x 4(n), 64x32 tiles
    const int wm1 = (warp >> 2) * 64, wn1 = (warp & 3) * 32;
    // phase-2/3 warp grid: 4(m) x 2(n), 32x32 tiles
    const int wm2 = (warp >> 1) * 32, wn2 = (warp & 1) * 32;

    const uint32_t sB0 = smem_u32(B0), sB1 = smem_u32(B1);

    // ===== phase 1: h1 = relu(edge @ W1^T + b1) =====
    for (int i = tid; i < 128 * 8; i += 256) {
        int row = i >> 3, c4 = (i & 7) * 4;
        float4 v = *(const float4*)(edge_data + (size_t)(m0 + row) * 32 + c4);
        __half h[4];
        h[0] = __float2half_rn(v.x); h[1] = __float2half_rn(v.y);
        h[2] = __float2half_rn(v.z); h[3] = __float2half_rn(v.w);
        *(uint2*)&EA[row * PA + c4] = *(uint2*)h;
    }
    for (int i = tid; i < 128 * 4; i += 256) {
        int row = i >> 2, c8 = (i & 3) * 8;
        *(uint4*)&W1s[row * PA + c8] = ((const uint4*)W1)[i];
    }
    // async prefetch W2 (both 64-col chunks)
    cpa_chunk(sB0, W2, tid);
    cpa_chunk(sB1, W2 + 64 * 128, tid);
    CPA_COMMIT;
    __syncthreads();

    {
        float c1[4][4][4];
        #pragma unroll
        for (int mt = 0; mt < 4; mt++)
            #pragma unroll
            for (int nt = 0; nt < 4; nt++)
                #pragma unroll
                for (int j = 0; j < 4; j++) c1[mt][nt][j] = 0.f;
        mma_block<2, PA, 4>(smem_u32(EA), smem_u32(W1s), lane, wm1, wn1, c1);
        epi_store<4>(c1, b1, H1, lane, wm1, wn1, 0);
    }
    CPA_WAIT0;
    __syncthreads();   // h1 + W2 chunks visible; phase-1 scratch reads done

    // ===== phase 2: h2 = relu(h1 @ W2^T + b2), two 64-col chunks =====
    #pragma unroll
    for (int ch = 0; ch < 2; ch++) {
        float c[2][4][4];
        #pragma unroll
        for (int mt = 0; mt < 2; mt++)
            #pragma unroll
            for (int nt = 0; nt < 4; nt++)
                #pragma unroll
                for (int j = 0; j < 4; j++) c[mt][nt][j] = 0.f;
        mma_block<8, P, 2>(smem_u32(H1), ch ? sB1 : sB0, lane, wm2, wn2, c);
        epi_store<2>(c, b2, H2, lane, wm2, wn2, ch * 64);
    }
    __syncthreads();   // all warps done with H1/WB; h2 written

    // ===== phase 3: layer-3 GEMM streamed in 64-col chunks, fused contraction =====
    for (int i = tid; i < 128 * 64; i += 256) {
        int row = i >> 6, as = i & 63;
        int e = m0 + row;
        int src = ei[e];
        u_s[row * 65 + as] = g_t[src * 16 + (as >> 2)] * sh[e * 4 + (as & 3)] * 0.125f;
    }
    for (int i = tid; i < NTOT; i += 256) bs[i] = b3[i];
    cpa_chunk(sB0, W3, tid);     // chunk 0
    CPA_COMMIT;

    float loc[4][NSLOT];
    #pragma unroll
    for (int s = 0; s < 4; s++)
        #pragma unroll
        for (int j = 0; j < NSLOT; j++) loc[s][j] = 0.f;

    const uint32_t sH2 = smem_u32(H2);

    for (int ch = 0; ch < NC; ch++) {
        CPA_WAIT0;
        __syncthreads();   // chunk ch visible; all warps done reading the other buffer
        if (ch + 1 < NC) {
            cpa_chunk((ch & 1) ? sB0 : sB1, W3 + (size_t)(ch + 1) * 64 * 128, tid);
            CPA_COMMIT;
        }

        float c[2][4][4];
        #pragma unroll
        for (int mt = 0; mt < 2; mt++)
            #pragma unroll
            for (int nt = 0; nt < 4; nt++)
                #pragma unroll
                for (int j = 0; j < 4; j++) c[mt][nt][j] = 0.f;
        mma_block<8, P, 2>(sH2, (ch & 1) ? sB1 : sB0, lane, wm2, wn2, c);

        #pragma unroll
        for (int mt = 0; mt < 2; mt++) {
            int r = wm2 + mt * 16 + (lane >> 2);
            #pragma unroll
            for (int nt = 0; nt < 4; nt++) {
                int colb = ch * 64 + wn2 + nt * 8;
                int as = (NOUT == 16) ? (colb >> 4) : (colb >> 3);
                int obi = (NOUT == 16) ? ((nt & 1) * 2) : 0;
                float ur = u_s[r * 65 + as];
                float ur8 = u_s[(r + 8) * 65 + as];
                loc[mt * 2][obi]         += c[mt][nt][0] * ur;
                loc[mt * 2][obi + 1]     += c[mt][nt][1] * ur;
                loc[mt * 2 + 1][obi]     += c[mt][nt][2] * ur8;
                loc[mt * 2 + 1][obi + 1] += c[mt][nt][3] * ur8;
            }
        }
    }
    __syncthreads();   // all warps done with B0 reads (part overlays B0)

    // per-warp partials -> smem (2 n-warps per row)
    {
        int wi = warp & 1;
        #pragma unroll
        for (int s = 0; s < 4; s++) {
            int row = wm2 + (s >> 1) * 16 + (s & 1) * 8 + (lane >> 2);
            #pragma unroll
            for (int j = 0; j < NSLOT; j++) {
                int ob = (lane & 3) * 2 + (j & 1) + (j >> 1) * 8;
                part[(wi * 128 + row) * PP + ob] = loc[s][j];
            }
        }
    }
    __syncthreads();

    if (NOUT == 16) {
        for (int idx = tid; idx < 128 * 16; idx += 256) {
            int row = idx >> 4, ob = idx & 15;
            float s = part[row * PP + ob] + part[(128 + row) * PP + ob];
            float bt = 0.f;
            #pragma unroll
            for (int as = 0; as < 64; as++) bt = fmaf(u_s[row * 65 + as], bs[as * 16 + ob], bt);
            g_vbuf[(size_t)(m0 + row) * 16 + ob] = s + bt;
        }
    } else {
        for (int idx = tid; idx < 128 * 8; idx += 256) {
            int row = idx >> 3, b = idx & 7;
            float s = part[row * PP + b] + part[(128 + row) * PP + b];
            float bt = 0.f;
            #pragma unroll
            for (int as = 0; as < 64; as++) bt = fmaf(u_s[row * 65 + as], bs[as * 8 + b], bt);
            part[row * PP + b] = s + bt;
        }
        __syncthreads();
        if (tid < 128) {
            int e = m0 + tid;
            int dst = ei[NE + e];
            float lp = 0.f;
            #pragma unroll
            for (int b = 0; b < 8; b++) lp += part[tid * PP + b] * g_qW[dst * 8 + b];
            g_logit[e] = lp;
            atomicMaxF(&g_m[dst], lp);
        }
    }
}

// one kernel runs the V chain then the K chain on the same 128 edges
__global__ __launch_bounds__(256, 2) void chain_both(
    const float* __restrict__ edge_data,
    const __half* __restrict__ Wv1, const float* __restrict__ bv1,
    const __half* __restrict__ Wv2, const float* __restrict__ bv2,
    const __half* __restrict__ Wv3, const float* __restrict__ bv3,
    const __half* __restrict__ Wk1, const float* __restrict__ bk1,
    const __half* __restrict__ Wk2, const float* __restrict__ bk2,
    const __half* __restrict__ Wk3, const float* __restrict__ bk3,
    const int* __restrict__ ei, const float* __restrict__ sh)
{
    extern __shared__ char sm[];
    chain_body<16, 8>(sm, edge_data, Wv1, bv1, Wv2, bv2, Wv3, bv3, ei, sh);
    __syncthreads();
    chain_body<8, 4>(sm, edge_data, Wk1, bk1, Wk2, bk2, Wk3, bk3, ei, sh);
}

// ---------------- init ----------------
__global__ void init_kernel() {
    int i = blockIdx.x * 256 + threadIdx.x;
    if (i < NN) { g_m[i] = -INFINITY; g_z[i] = 0.f; }
    if (i < NN * 16) g_agg[i] = 0.f;
    if (i < 64) { g_colsum[i] = 0.f; g_colsumsq[i] = 0.f; }
}

// ---------------- node linears ----------------
__global__ __launch_bounds__(128) void node_kernel(
    const float* __restrict__ node_data, const float* __restrict__ W_input,
    const float* __restrict__ W_query, const float* __restrict__ W_dot)
{
    __shared__ float Wi[64 * 16];
    __shared__ float Wq[16 * 8];
    __shared__ float Wd[64];
    __shared__ float tsh[8][16];
    __shared__ float qsh[8][8];
    int tid = threadIdx.x;
    for (int i = tid; i < 1024; i += 128) Wi[i] = W_input[i];
    if (tid < 128) Wq[tid] = W_query[tid];
    if (tid < 64) Wd[tid] = W_dot[tid];
    __syncthreads();

    int n_loc = tid >> 4, c = tid & 15;
    int n = blockIdx.x * 8 + n_loc;
    float tv = 0.f;
    if (n < NN) {
        const float* nd = node_data + (size_t)n * 64;
        #pragma unroll 8
        for (int i = 0; i < 64; i++) tv += nd[i] * Wi[i * 16 + c];
        tv *= 0.125f;
        g_t[n * 16 + c] = tv;
    }
    tsh[n_loc][c] = tv;
    __syncthreads();

    if (tid < 64) {
        int nl = tid >> 3, b = tid & 7;
        float qv = 0.f;
        #pragma unroll
        for (int a = 0; a < 16; a++) qv += tsh[nl][a] * Wq[a * 8 + b];
        qsh[nl][b] = qv * 0.25f;
    }
    __syncthreads();
    if (tid < 64) {
        int nl = tid >> 3, b = tid & 7;
        int n2 = blockIdx.x * 8 + nl;
        if (n2 < NN) {
            float s = 0.f;
            #pragma unroll
            for (int a = 0; a < 8; a++) s += qsh[nl][a] * Wd[a * 8 + b];
            g_qW[n2 * 8 + b] = s * 0.125f;
        }
    }
}

// ---------------- softmax numerator + segment sums ----------------
__global__ void attn_agg_kernel(const int* __restrict__ ei)
{
    int e = blockIdx.x * 256 + threadIdx.x;
    if (e >= NE) return;
    int dst = ei[NE + e];
    float p = expf(g_logit[e] - g_m[dst]);
    atomicAdd(&g_z[dst], p);
    const float* v = g_vbuf + (size_t)e * 16;
    float* agg = g_agg + dst * 16;
    #pragma unroll
    for (int c = 0; c < 16; c++) atomicAdd(&agg[c], p * v[c]);
}

// ---------------- output linear + residual + BN stats ----------------
__global__ __launch_bounds__(256) void out_stats_kernel(
    const float* __restrict__ node_data, const float* __restrict__ W_output)
{
    __shared__ float Wsh[16 * 64];
    __shared__ float red[256];
    int tid = threadIdx.x;
    for (int i = tid; i < 1024; i += 256) Wsh[i] = W_output[i];
    __syncthreads();

    int c = tid & 63;
    int r = tid >> 6;
    int n0 = blockIdx.x * 64;
    float lsum = 0.f, lsq = 0.f;
    for (int i = 0; i < 16; i++) {
        int n = n0 + r + i * 4;
        if (n < NN) {
            float zz = g_z[n];
            float inv = zz > 0.f ? 0.25f / zz : 0.f;
            float o = 0.f;
            const float* agg = g_agg + n * 16;
            #pragma unroll
            for (int j = 0; j < 16; j++) o += agg[j] * Wsh[j * 64 + c];
            o = o * inv + node_data[(size_t)n * 64 + c];
            g_outpre[(size_t)n * 64 + c] = o;
            lsum += o;
            lsq += o * o;
        }
    }
    red[tid] = lsum;
    __syncthreads();
    if (r == 0) atomicAdd(&g_colsum[c], red[c] + red[64 + c] + red[128 + c] + red[192 + c]);
    __syncthreads();
    red[tid] = lsq;
    __syncthreads();
    if (r == 0) atomicAdd(&g_colsumsq[c], red[c] + red[64 + c] + red[128 + c] + red[192 + c]);
}

// ---------------- batchnorm finalize ----------------
__global__ void bn_kernel(const float* __restrict__ bnw, const float* __restrict__ bnb,
                          float* __restrict__ out)
{
    int i = blockIdx.x * 256 + threadIdx.x;
    if (i >= NN * 64) return;
    int c = i & 63;
    const float invN = 1.f / NN;
    float mean = g_colsum[c] * invN;
    float var = g_colsumsq[c] * invN - mean * mean;
    out[i] = (g_outpre[i] - mean) * rsqrtf(var + 1e-5f) * bnw[c] + bnb[c];
}

// ---------------- launch ----------------
extern "C" void kernel_launch(void* const* d_in, const int* in_sizes, int n_in,
                              void* d_out, int out_size)
{
    const float* node_data = (const float*)d_in[0];
    const int*   edge_index = (const int*)d_in[1];
    const float* edge_data = (const float*)d_in[2];
    const float* edge_sh   = (const float*)d_in[3];
    const float* W_input = (const float*)d_in[4];
    const float* W_query = (const float*)d_in[5];
    const float* W_dot   = (const float*)d_in[6];
    const float* W_output = (const float*)d_in[7];
    const float* Wk1 = (const float*)d_in[8];
    const float* bk1 = (const float*)d_in[9];
    const float* Wk2 = (const float*)d_in[10];
    const float* bk2 = (const float*)d_in[11];
    const float* Wk3 = (const float*)d_in[12];
    const float* bk3 = (const float*)d_in[13];
    const float* Wv1 = (const float*)d_in[14];
    const float* bv1 = (const float*)d_in[15];
    const float* Wv2 = (const float*)d_in[16];
    const float* bv2 = (const float*)d_in[17];
    const float* Wv3 = (const float*)d_in[18];
    const float* bv3 = (const float*)d_in[19];
    const float* bn_weight = (const float*)d_in[20];
    const float* bn_bias   = (const float*)d_in[21];
    float* out = (float*)d_out;

    void *pw1k, *pw1v, *pw2k, *pw2v, *pw3k, *pw3v;
    cudaGetSymbolAddress(&pw1k, g_w1k); cudaGetSymbolAddress(&pw1v, g_w1v);
    cudaGetSymbolAddress(&pw2k, g_w2k); cudaGetSymbolAddress(&pw2v, g_w2v);
    cudaGetSymbolAddress(&pw3k, g_w3k); cudaGetSymbolAddress(&pw3v, g_w3v);

    const int SMC = 108544;
    cudaFuncSetAttribute(chain_both, cudaFuncAttributeMaxDynamicSharedMemorySize, SMC);

    init_kernel<<<(NE + 255) / 256, 256>>>();                                   // 0
    wconv_all<<<(237568 + 255) / 256, 256>>>(Wk1, Wv1, Wk2, Wv2, Wk3, Wv3);     // 1
    node_kernel<<<(NN + 7) / 8, 128>>>(node_data, W_input, W_query, W_dot);     // 2
    chain_both<<<NE / 128, 256, SMC>>>(                                         // 3
        edge_data,
        (const __half*)pw1v, bv1, (const __half*)pw2v, bv2, (const __half*)pw3v, bv3,
        (const __half*)pw1k, bk1, (const __half*)pw2k, bk2, (const __half*)pw3k, bk3,
        edge_index, edge_sh);

    attn_agg_kernel<<<(NE + 255) / 256, 256>>>(edge_index);                     // 4
    out_stats_kernel<<<(NN + 63) / 64, 256>>>(node_data, W_output);             // 5
    bn_kernel<<<(NN * 64 + 255) / 256, 256>>>(bn_weight, bn_bias, out);         // 6
}